// round 4
// baseline (speedup 1.0000x reference)
#include <cuda_runtime.h>

// ---------------- problem constants ----------------
#define NN 15000          // nodes
#define NE 60000          // edges
#define ND 64             // NODE_DIM
#define HD 64             // HID
#define ED 33             // EDGE_DIM
#define CT 4160           // 65*64 columns of M (j=0..63 from w2, j=64 = b2 row)
#define G  16             // nodes per fused block
#define ECAP 128          // edge slots per pass

typedef unsigned long long ull;

__device__ __forceinline__ ull ffma2(ull a, ull b, ull c) {
    ull d;
    asm("fma.rn.f32x2 %0, %1, %2, %3;" : "=l"(d) : "l"(a), "l"(b), "l"(c));
    return d;
}
__device__ __forceinline__ ull dup2(float x) {
    ull d;
    asm("mov.b64 %0, {%1, %1};" : "=l"(d) : "f"(x));
    return d;
}
__device__ __forceinline__ void cp_async16(void* smem_dst, const void* gsrc) {
    unsigned saddr = (unsigned)__cvta_generic_to_shared(smem_dst);
    asm volatile("cp.async.cg.shared.global [%0], [%1], 16;" :: "r"(saddr), "l"(gsrc));
}
__device__ __forceinline__ void cp_commit() { asm volatile("cp.async.commit_group;"); }
template <int N> __device__ __forceinline__ void cp_wait() {
    asm volatile("cp.async.wait_group %0;" :: "n"(N));
}

// ---------------- device scratch ----------------
__device__ float g_xf[NN * ND];
__device__ float g_h[NE * HD];
__device__ float g_M[ND * CT];           // M[i][j*64+o] = w2[j, i*64+o]; row j=64 = b2
__device__ float g_sums[NN * HD];
__device__ int   g_dcnt[NN];
__device__ int   g_hist[NN];
__device__ int   g_off[NN + 1];
__device__ int   g_cursor[NN];
__device__ int   g_sorted[NE];

// ---------------- L0: build M + zero accumulators ----------------
__global__ void k_init(const float* __restrict__ w2, const float* __restrict__ b2) {
    int idx = blockIdx.x * blockDim.x + threadIdx.x;
    if (idx < ND * CT) {
        int i = idx / CT;
        int col = idx - i * CT;
        int j = col >> 6;
        int o = col & 63;
        g_M[idx] = (j < 64) ? w2[j * 4096 + i * 64 + o] : b2[i * 64 + o];
    }
    if (idx < NN * HD) g_sums[idx] = 0.f;
    if (idx < NN) { g_hist[idx] = 0; g_dcnt[idx] = 0; }
}

// ---------------- L1: node features + degree histograms + edge MLP ----------------
#define NB_NODE 1875
#define NB_HIST 235
#define NB_MLP  7500
__global__ void k_prep(const float* __restrict__ x,
                       const int* __restrict__ inp, const int* __restrict__ outp,
                       const float* __restrict__ in_emb, const float* __restrict__ out_emb,
                       const int* __restrict__ eidx,
                       const int* __restrict__ e_nt, const int* __restrict__ e_np,
                       const float* __restrict__ e_sc,
                       const float* __restrict__ nt_emb, const float* __restrict__ np_emb,
                       const float* __restrict__ w1, const float* __restrict__ b1) {
    int b = blockIdx.x;
    int tid = threadIdx.x;
    if (b < NB_NODE) {                       // node features
        int w = tid >> 5, l = tid & 31;
        int n = b * 8 + w;
        if (n >= NN) return;
        float v0 = x[n * 32 + l];
        float v1 = (l < 16) ? in_emb[inp[n] * 16 + l]
                            : out_emb[outp[n] * 16 + (l - 16)];
        g_xf[n * 64 + l] = v0;
        g_xf[n * 64 + 32 + l] = v1;
        return;
    }
    if (b < NB_NODE + NB_HIST) {             // degree histograms
        int e = (b - NB_NODE) * 256 + tid;
        if (e >= NE) return;
        atomicAdd(&g_hist[eidx[e]], 1);
        atomicAdd(&g_dcnt[eidx[NE + e]], 1);
        return;
    }
    // edge MLP: h = relu(ea @ w1 + b1), 1 warp / edge
    __shared__ float w1s[ED * 64];
    __shared__ float b1s[64];
    __shared__ float eas[8][34];
    for (int i = tid; i < ED * 64; i += 256) w1s[i] = w1[i];
    if (tid < 64) b1s[tid] = b1[tid];
    __syncthreads();
    int w = tid >> 5, l = tid & 31;
    int e = (b - NB_NODE - NB_HIST) * 8 + w;
    if (e >= NE) return;
    if (l < 16) eas[w][l] = nt_emb[e_nt[e] * 16 + l];
    else        eas[w][l] = np_emb[e_np[e] * 16 + (l - 16)];
    if (l == 0) eas[w][32] = e_sc[e];
    __syncwarp();
    int o0 = l, o1 = l + 32;
    float a0 = b1s[o0], a1 = b1s[o1];
#pragma unroll
    for (int k = 0; k < ED; k++) {
        float v = eas[w][k];
        a0 = fmaf(v, w1s[k * 64 + o0], a0);
        a1 = fmaf(v, w1s[k * 64 + o1], a1);
    }
    g_h[e * 64 + o0] = fmaxf(a0, 0.f);
    g_h[e * 64 + o1] = fmaxf(a1, 0.f);
}

// ---------------- L2: CSR scan + scatter (single block) ----------------
__global__ void k_scanscatter(const int* __restrict__ eidx) {
    __shared__ int warp_sums[32];
    __shared__ int s_carry;
    int tid = threadIdx.x;
    int lane = tid & 31, wid = tid >> 5;
    if (tid == 0) { s_carry = 0; g_off[0] = 0; }
    __syncthreads();
    for (int base = 0; base < NN; base += 1024) {
        int i = base + tid;
        int v = (i < NN) ? g_hist[i] : 0;
        int xv = v;
#pragma unroll
        for (int d = 1; d < 32; d <<= 1) {
            int y = __shfl_up_sync(0xffffffffu, xv, d);
            if (lane >= d) xv += y;
        }
        if (lane == 31) warp_sums[wid] = xv;
        __syncthreads();
        if (tid < 32) {
            int w = warp_sums[tid];
#pragma unroll
            for (int d = 1; d < 32; d <<= 1) {
                int y = __shfl_up_sync(0xffffffffu, w, d);
                if (tid >= d) w += y;
            }
            warp_sums[tid] = w;
        }
        __syncthreads();
        int incl = xv + ((wid > 0) ? warp_sums[wid - 1] : 0) + s_carry;
        if (i < NN) { g_off[i + 1] = incl; g_cursor[i] = incl - v; }
        __syncthreads();
        if (tid == 0) s_carry += warp_sums[31];
        __syncthreads();
    }
    // scatter
    for (int e = tid; e < NE; e += 1024) {
        int pos = atomicAdd(&g_cursor[eidx[e]], 1);
        g_sorted[pos] = e;
    }
}

// ---------------- L3: FUSED per-node GEMM + edge apply (no g_T!) ----------------
// Block: 16 src nodes, 128 threads. For each j in 0..64:
//   phase A: tmp[n][o] = sum_i xf[n][i] * M[i][j*64+o]   (FFMA2, 8 o/thread)
//   phase B: msg[e][o] += h[e][j] * tmp[nloc(e)][o]      (regs, thread = edge slot)
// smem floats: Mt[2][64*68] | xf[16*64] | tmp[2][16*68] | hT[65*128] | es[128]
#define SM_MT   0
#define SM_XF   (2 * 64 * 68)            // 8704
#define SM_TMP  (SM_XF + 16 * 64)        // 9728
#define SM_HT   (SM_TMP + 2 * 16 * 68)   // 11904
#define SM_ES   (SM_HT + 65 * 128)       // 20224
#define SM_FUSED_BYTES ((SM_ES + 128) * 4)

__global__ __launch_bounds__(128) void k_fused(const int* __restrict__ eidx) {
    extern __shared__ float sm[];
    float* MtB = sm + SM_MT;
    float* xfs = sm + SM_XF;
    float* tmpB = sm + SM_TMP;
    float* hT = sm + SM_HT;
    int* es = (int*)(sm + SM_ES);

    int tid = threadIdx.x;
    int n0 = blockIdx.x * G;
    int beg = g_off[n0];
    int end = g_off[min(n0 + G, NN)];
    if (beg == end) return;

    // xf for the 16 nodes
    for (int idx = tid; idx < G * 64; idx += 128) {
        int n = idx >> 6, c = idx & 63;
        xfs[idx] = (n0 + n < NN) ? g_xf[(n0 + n) * 64 + c] : 0.f;
    }

    // phase-A thread mapping: n = tid>>3 (16 nodes), o0 = (tid&7)*8
    int an = tid >> 3;
    int ao = (tid & 7) * 8;

    for (int pbeg = beg; pbeg < end; pbeg += ECAP) {
        int E_act = min(end - pbeg, ECAP);

        int e = -1, nloc = 0, dstv = -1;
        if (tid < E_act) {
            e = g_sorted[pbeg + tid];
            es[tid] = e;
            nloc = eidx[e] - n0;
            dstv = eidx[NE + e];
        }
        __syncthreads();

        // load h transposed: hT[j][s]
        for (int idx = tid; idx < E_act * 16; idx += 128) {
            int s = idx >> 4, q = idx & 15;
            float4 v = *(const float4*)(g_h + (size_t)es[s] * 64 + q * 4);
            hT[(4 * q + 0) * 128 + s] = v.x;
            hT[(4 * q + 1) * 128 + s] = v.y;
            hT[(4 * q + 2) * 128 + s] = v.z;
            hT[(4 * q + 3) * 128 + s] = v.w;
        }
        hT[64 * 128 + tid] = 1.f;    // bias row: h'[64] = 1

        // message accumulators (64 outputs as 32 packed pairs)
        ull macc[32];
#pragma unroll
        for (int q = 0; q < 32; q++) macc[q] = 0ull;

        // prefetch M tile for j=0
        {
            float* dst = MtB;
#pragma unroll
            for (int q = 0; q < 8; q++) {
                int idx = q * 128 + tid;
                int r = idx >> 4, c = idx & 15;
                cp_async16(dst + r * 68 + c * 4, g_M + r * CT + c * 4);
            }
            cp_commit();
        }
        __syncthreads();

        for (int j = 0; j < 65; j++) {
            int buf = j & 1;
            if (j < 64) {   // prefetch j+1
                float* dst = MtB + ((j + 1) & 1) * (64 * 68);
                const float* src = g_M + (j + 1) * 64;
#pragma unroll
                for (int q = 0; q < 8; q++) {
                    int idx = q * 128 + tid;
                    int r = idx >> 4, c = idx & 15;
                    cp_async16(dst + r * 68 + c * 4, src + r * CT + c * 4);
                }
                cp_commit();
                cp_wait<1>();
            } else {
                cp_wait<0>();
            }
            __syncthreads();

            // ---- phase A: tmp[n][o0..o0+7] ----
            {
                const float* mt = MtB + buf * (64 * 68) + ao;
                const float* xr = xfs + an * 64;
                ull a0 = 0, a1 = 0, a2 = 0, a3 = 0;
#pragma unroll 8
                for (int i = 0; i < 64; i++) {
                    ull xv = dup2(xr[i]);
                    ulonglong2 mlo = *(const ulonglong2*)(mt + i * 68);
                    ulonglong2 mhi = *(const ulonglong2*)(mt + i * 68 + 4);
                    a0 = ffma2(xv, mlo.x, a0);
                    a1 = ffma2(xv, mlo.y, a1);
                    a2 = ffma2(xv, mhi.x, a2);
                    a3 = ffma2(xv, mhi.y, a3);
                }
                float* tr = tmpB + buf * (16 * 68) + an * 68 + ao;
                *(ulonglong2*)tr = make_ulonglong2(a0, a1);
                *(ulonglong2*)(tr + 4) = make_ulonglong2(a2, a3);
            }
            __syncthreads();

            // ---- phase B: msg += h[j] * tmp[nloc] ----
            if (e >= 0) {
                ull h2 = dup2(hT[j * 128 + tid]);
                const float* tr = tmpB + buf * (16 * 68) + nloc * 68;
#pragma unroll
                for (int q = 0; q < 16; q++) {
                    ulonglong2 t2 = *(const ulonglong2*)(tr + q * 4);
                    macc[2 * q] = ffma2(h2, t2.x, macc[2 * q]);
                    macc[2 * q + 1] = ffma2(h2, t2.y, macc[2 * q + 1]);
                }
            }
        }

        // scatter-add messages
        if (dstv >= 0) {
            float* sp = g_sums + (size_t)dstv * 64;
#pragma unroll
            for (int q = 0; q < 32; q++) {
                atomicAdd(sp + 2 * q, __uint_as_float((unsigned)macc[q]));
                atomicAdd(sp + 2 * q + 1, __uint_as_float((unsigned)(macc[q] >> 32)));
            }
        }
        __syncthreads();   // protect es/hT for next pass
    }
}

// ---------------- L4: scatter-mean + root + ReLU + 4 heads ----------------
__global__ void k_final(const float* __restrict__ root_w, const float* __restrict__ conv_b,
                        const float* __restrict__ wsu, const float* __restrict__ bsu,
                        const float* __restrict__ wnt, const float* __restrict__ bnt,
                        const float* __restrict__ wtg, const float* __restrict__ btg,
                        const float* __restrict__ wpr, const float* __restrict__ bpr,
                        float* __restrict__ out) {
    extern __shared__ float sm[];
    float* rw = sm;                  // 4096
    float* cb = rw + 4096;           // 64
    float* Wc = cb + 64;             // 64*240
    float* bc = Wc + 64 * 240;       // 240
    float* stage = bc + 240;         // 8 * 128
    int tid = threadIdx.x;
    for (int i = tid; i < 4096; i += 256) rw[i] = root_w[i];
    if (tid < 64) cb[tid] = conv_b[tid];
    for (int i = tid; i < 64 * 16; i += 256)  { int r = i >> 4, c = i & 15;  Wc[r * 240 + c]       = wsu[i]; }
    for (int i = tid; i < 64 * 32; i += 256)  { int r = i >> 5, c = i & 31;  Wc[r * 240 + 16 + c]  = wnt[i]; }
    for (int i = tid; i < 64 * 64; i += 256)  { int r = i >> 6, c = i & 63;  Wc[r * 240 + 48 + c]  = wtg[i]; }
    for (int i = tid; i < 64 * 128; i += 256) { int r = i >> 7, c = i & 127; Wc[r * 240 + 112 + c] = wpr[i]; }
    if (tid < 16)       bc[tid] = bsu[tid];
    else if (tid < 48)  bc[tid] = bnt[tid - 16];
    else if (tid < 112) bc[tid] = btg[tid - 48];
    else if (tid < 240) bc[tid] = bpr[tid - 112];
    __syncthreads();

    int w = tid >> 5, l = tid & 31;
    int n = blockIdx.x * 8 + w;
    if (n >= NN) return;
    float* xs = stage + w * 128;
    float* os = xs + 64;
    xs[l] = g_xf[n * 64 + l];
    xs[l + 32] = g_xf[n * 64 + 32 + l];
    __syncwarp();

    float inv = 1.f / fmaxf((float)g_dcnt[n], 1.f);
#pragma unroll
    for (int half = 0; half < 2; half++) {
        int o = l + 32 * half;
        float acc = cb[o] + g_sums[n * 64 + o] * inv;
#pragma unroll 8
        for (int i = 0; i < 64; i++) acc = fmaf(xs[i], rw[i * 64 + o], acc);
        os[o] = fmaxf(acc, 0.f);
    }
    __syncwarp();

#pragma unroll
    for (int q = 0; q < 8; q++) {
        int t = l + 32 * q;
        if (t < 240) {
            float acc = bc[t];
#pragma unroll 8
            for (int i = 0; i < 64; i++) acc = fmaf(os[i], Wc[i * 240 + t], acc);
            if (t < 16)       out[n * 16 + t] = acc;
            else if (t < 48)  out[240000  + n * 32  + (t - 16)]  = acc;
            else if (t < 112) out[720000  + n * 64  + (t - 48)]  = acc;
            else              out[1680000 + n * 128 + (t - 112)] = acc;
        }
    }
}

// ---------------- launch ----------------
extern "C" void kernel_launch(void* const* d_in, const int* in_sizes, int n_in,
                              void* d_out, int out_size) {
    const float* x        = (const float*)d_in[0];
    const int*   input_np = (const int*)  d_in[1];
    const int*   output_np= (const int*)  d_in[2];
    const int*   edge_idx = (const int*)  d_in[3];
    const int*   edge_nt  = (const int*)  d_in[4];
    const int*   edge_np  = (const int*)  d_in[5];
    const float* edge_sc  = (const float*)d_in[6];
    const float* in_emb   = (const float*)d_in[7];
    const float* out_emb  = (const float*)d_in[8];
    const float* enp_emb  = (const float*)d_in[9];
    const float* ent_emb  = (const float*)d_in[10];
    const float* w1       = (const float*)d_in[11];
    const float* b1       = (const float*)d_in[12];
    const float* w2       = (const float*)d_in[13];
    const float* b2       = (const float*)d_in[14];
    const float* root_w   = (const float*)d_in[15];
    const float* conv_b   = (const float*)d_in[16];
    const float* wsu      = (const float*)d_in[17];
    const float* bsu      = (const float*)d_in[18];
    const float* wnt      = (const float*)d_in[19];
    const float* bnt      = (const float*)d_in[20];
    const float* wtg      = (const float*)d_in[21];
    const float* btg      = (const float*)d_in[22];
    const float* wpr      = (const float*)d_in[23];
    const float* bpr      = (const float*)d_in[24];
    float* out = (float*)d_out;

    const int smem_final = (4096 + 64 + 64 * 240 + 240 + 8 * 128) * 4;     // 83136 B
    cudaFuncSetAttribute(k_fused, cudaFuncAttributeMaxDynamicSharedMemorySize, SM_FUSED_BYTES);
    cudaFuncSetAttribute(k_final, cudaFuncAttributeMaxDynamicSharedMemorySize, smem_final);

    k_init<<<(NN * HD + 255) / 256, 256>>>(w2, b2);                        // idx 0
    k_prep<<<NB_NODE + NB_HIST + NB_MLP, 256>>>(x, input_np, output_np,    // idx 1
            in_emb, out_emb, edge_idx, edge_nt, edge_np, edge_sc,
            ent_emb, enp_emb, w1, b1);
    k_scanscatter<<<1, 1024>>>(edge_idx);                                  // idx 2
    k_fused<<<(NN + G - 1) / G, 128, SM_FUSED_BYTES>>>(edge_idx);          // idx 3 (profiled)
    k_final<<<(NN + 7) / 8, 256, smem_final>>>(root_w, conv_b,             // idx 4
            wsu, bsu, wnt, bnt, wtg, btg, wpr, bpr, out);
}

// round 5
// speedup vs baseline: 2.1532x; 2.1532x over previous
#include <cuda_runtime.h>

// ---------------- problem constants ----------------
#define NN 15000          // nodes
#define NE 60000          // edges
#define ND 64             // NODE_DIM
#define HD 64             // HID
#define ED 33             // EDGE_DIM
#define CT 4160           // 65*64 columns of M (j=0..63 from w2, j=64 = b2 row)

typedef unsigned long long ull;

__device__ __forceinline__ ull ffma2(ull a, ull b, ull c) {
    ull d;
    asm("fma.rn.f32x2 %0, %1, %2, %3;" : "=l"(d) : "l"(a), "l"(b), "l"(c));
    return d;
}
__device__ __forceinline__ ull dup2(float x) {
    ull d;
    asm("mov.b64 %0, {%1, %1};" : "=l"(d) : "f"(x));
    return d;
}

// ---------------- device scratch ----------------
__device__ float g_xf[NN * ND];
__device__ float g_h[NE * HD];
__device__ float g_M[ND * CT];           // M[i][j*64+o] = w2[j, i*64+o]; row j=64 = b2
__device__ float g_T[(size_t)NN * CT];   // per-node tensor (249.6 MB)
__device__ float g_sums[NN * HD];
__device__ int   g_dcnt[NN];
__device__ int   g_hist[NN];
__device__ int   g_off[NN + 1];
__device__ int   g_cursor[NN];
__device__ int   g_sorted[NE];

// ---------------- L0: build M + zero accumulators ----------------
__global__ void k_init(const float* __restrict__ w2, const float* __restrict__ b2) {
    int idx = blockIdx.x * blockDim.x + threadIdx.x;
    if (idx < ND * CT) {
        int i = idx / CT;
        int col = idx - i * CT;
        int j = col >> 6;
        int o = col & 63;
        g_M[idx] = (j < 64) ? w2[j * 4096 + i * 64 + o] : b2[i * 64 + o];
    }
    if (idx < NN * HD) g_sums[idx] = 0.f;
    if (idx < NN) { g_hist[idx] = 0; g_dcnt[idx] = 0; }
}

// ---------------- L1: node features + degree histograms + edge MLP ----------------
#define NB_NODE 1875
#define NB_HIST 235
#define NB_MLP  7500
__global__ void k_prep(const float* __restrict__ x,
                       const int* __restrict__ inp, const int* __restrict__ outp,
                       const float* __restrict__ in_emb, const float* __restrict__ out_emb,
                       const int* __restrict__ eidx,
                       const int* __restrict__ e_nt, const int* __restrict__ e_np,
                       const float* __restrict__ e_sc,
                       const float* __restrict__ nt_emb, const float* __restrict__ np_emb,
                       const float* __restrict__ w1, const float* __restrict__ b1) {
    int b = blockIdx.x;
    int tid = threadIdx.x;
    if (b < NB_NODE) {                       // node features
        int w = tid >> 5, l = tid & 31;
        int n = b * 8 + w;
        if (n >= NN) return;
        float v0 = x[n * 32 + l];
        float v1 = (l < 16) ? in_emb[inp[n] * 16 + l]
                            : out_emb[outp[n] * 16 + (l - 16)];
        g_xf[n * 64 + l] = v0;
        g_xf[n * 64 + 32 + l] = v1;
        return;
    }
    if (b < NB_NODE + NB_HIST) {             // degree histograms
        int e = (b - NB_NODE) * 256 + tid;
        if (e >= NE) return;
        atomicAdd(&g_hist[eidx[e]], 1);
        atomicAdd(&g_dcnt[eidx[NE + e]], 1);
        return;
    }
    // edge MLP: h = relu(ea @ w1 + b1), 1 warp / edge
    __shared__ float w1s[ED * 64];
    __shared__ float b1s[64];
    __shared__ float eas[8][34];
    for (int i = tid; i < ED * 64; i += 256) w1s[i] = w1[i];
    if (tid < 64) b1s[tid] = b1[tid];
    __syncthreads();
    int w = tid >> 5, l = tid & 31;
    int e = (b - NB_NODE - NB_HIST) * 8 + w;
    if (e >= NE) return;
    if (l < 16) eas[w][l] = nt_emb[e_nt[e] * 16 + l];
    else        eas[w][l] = np_emb[e_np[e] * 16 + (l - 16)];
    if (l == 0) eas[w][32] = e_sc[e];
    __syncwarp();
    int o0 = l, o1 = l + 32;
    float a0 = b1s[o0], a1 = b1s[o1];
#pragma unroll
    for (int k = 0; k < ED; k++) {
        float v = eas[w][k];
        a0 = fmaf(v, w1s[k * 64 + o0], a0);
        a1 = fmaf(v, w1s[k * 64 + o1], a1);
    }
    g_h[e * 64 + o0] = fmaxf(a0, 0.f);
    g_h[e * 64 + o1] = fmaxf(a1, 0.f);
}

// ---------------- L2: CSR scan + scatter (single block) ----------------
__global__ void k_scanscatter(const int* __restrict__ eidx) {
    __shared__ int warp_sums[32];
    __shared__ int s_carry;
    int tid = threadIdx.x;
    int lane = tid & 31, wid = tid >> 5;
    if (tid == 0) { s_carry = 0; g_off[0] = 0; }
    __syncthreads();
    for (int base = 0; base < NN; base += 1024) {
        int i = base + tid;
        int v = (i < NN) ? g_hist[i] : 0;
        int xv = v;
#pragma unroll
        for (int d = 1; d < 32; d <<= 1) {
            int y = __shfl_up_sync(0xffffffffu, xv, d);
            if (lane >= d) xv += y;
        }
        if (lane == 31) warp_sums[wid] = xv;
        __syncthreads();
        if (tid < 32) {
            int w = warp_sums[tid];
#pragma unroll
            for (int d = 1; d < 32; d <<= 1) {
                int y = __shfl_up_sync(0xffffffffu, w, d);
                if (tid >= d) w += y;
            }
            warp_sums[tid] = w;
        }
        __syncthreads();
        int incl = xv + ((wid > 0) ? warp_sums[wid - 1] : 0) + s_carry;
        if (i < NN) { g_off[i + 1] = incl; g_cursor[i] = incl - v; }
        __syncthreads();
        if (tid == 0) s_carry += warp_sums[31];
        __syncthreads();
    }
    for (int e = tid; e < NE; e += 1024) {
        int pos = atomicAdd(&g_cursor[eidx[e]], 1);
        g_sorted[pos] = e;
    }
}

// ---------------- L3: GEMM  T[NN, CT] = g_xf[NN,64] @ g_M[64, CT] ----------------
// Tile 128m x 64n, K=64, 256 threads, 4m x 8n per thread via FFMA2.
// smem = 50176 B -> 4 blocks/SM (32 warps) for latency hiding.
__global__ __launch_bounds__(256) void k_gemm() {
    extern __shared__ float sm[];
    float* At = sm;              // [64][132]  k-major, m stride 1, pad 132
    float* Bs = sm + 64 * 132;   // [64][64]
    int tid = threadIdx.x;
    int c0 = blockIdx.x * 64;
    int r0 = blockIdx.y * 128;

    // A load: 2 threads per row; transpose into At[k][m]
    {
        int row = tid >> 1, half = tid & 1;
        int gr = r0 + row;
        if (gr < NN) {
            const float4* ap = (const float4*)(g_xf + gr * 64 + half * 32);
#pragma unroll
            for (int q = 0; q < 8; q++) {
                float4 v = ap[q];
                int k = half * 32 + 4 * q;
                At[(k + 0) * 132 + row] = v.x;
                At[(k + 1) * 132 + row] = v.y;
                At[(k + 2) * 132 + row] = v.z;
                At[(k + 3) * 132 + row] = v.w;
            }
        } else {
#pragma unroll
            for (int q = 0; q < 32; q++) At[(half * 32 + q) * 132 + row] = 0.f;
        }
    }
    // B load
#pragma unroll
    for (int q = 0; q < 4; q++) {
        int idx = q * 256 + tid;          // float4 index, 1024 total
        int k = idx >> 4;
        int c = idx & 15;
        ((float4*)Bs)[k * 16 + c] = *(const float4*)&g_M[k * CT + c0 + c * 4];
    }
    __syncthreads();

    int m0 = (tid >> 3) * 4;   // 32 m-groups -> 128 rows
    int n0 = (tid & 7) * 8;    // 8 n-groups  -> 64 cols
    ull acc[4][4];
#pragma unroll
    for (int i = 0; i < 4; i++)
#pragma unroll
        for (int j = 0; j < 4; j++) acc[i][j] = 0ull;

#pragma unroll 8
    for (int k = 0; k < 64; k++) {
        float4 av = *(const float4*)&At[k * 132 + m0];
        ulonglong2 b0 = *(const ulonglong2*)&Bs[k * 64 + n0];
        ulonglong2 b1 = *(const ulonglong2*)&Bs[k * 64 + n0 + 4];
        ull ad[4] = {dup2(av.x), dup2(av.y), dup2(av.z), dup2(av.w)};
        ull bp[4] = {b0.x, b0.y, b1.x, b1.y};
#pragma unroll
        for (int i = 0; i < 4; i++)
#pragma unroll
            for (int j = 0; j < 4; j++)
                acc[i][j] = ffma2(ad[i], bp[j], acc[i][j]);
    }
#pragma unroll
    for (int i = 0; i < 4; i++) {
        int row = r0 + m0 + i;
        if (row < NN) {
            ulonglong2* dp = (ulonglong2*)(g_T + (size_t)row * CT + c0 + n0);
            dp[0] = make_ulonglong2(acc[i][0], acc[i][1]);
            dp[1] = make_ulonglong2(acc[i][2], acc[i][3]);
        }
    }
}

// ---------------- L4: per-src-node edge apply (1 block / node, T row in smem) ----------------
__global__ void k_edge_apply(const int* __restrict__ eidx) {
    __shared__ __align__(16) float ts[CT];     // 16640 B (T row for this src)
    __shared__ ull hd[8][64];                  // 4096 B (packed dup h per edge)
    __shared__ int dsts[8];
    int n = blockIdx.x;
    int beg = g_off[n], end = g_off[n + 1];
    if (beg == end) return;
    int tid = threadIdx.x;                     // 128 threads
    const float4* Tp = (const float4*)(g_T + (size_t)n * CT);
    float4* tsp = (float4*)ts;
    for (int i = tid; i < CT / 4; i += 128) tsp[i] = Tp[i];
    __syncthreads();

    int q = tid >> 4;          // edge slot 0..7
    int l16 = tid & 15;
    int o = l16 * 4;           // 4 outputs o..o+3
    const ulonglong2* ts2 = (const ulonglong2*)ts;

    for (int p = beg; p < end; p += 8) {
        int idx = p + q;
        int e = -1;
        if (idx < end) {
            e = g_sorted[idx];
            const float* hp = g_h + e * 64;
#pragma unroll
            for (int t = 0; t < 4; t++) hd[q][o + t] = dup2(hp[o + t]);
            if (l16 == 0) dsts[q] = eidx[NE + e];
        }
        __syncthreads();
        if (e >= 0) {
            ull acc0 = *(const ull*)&ts[4096 + o];      // b2 row (h'[64]=1)
            ull acc1 = *(const ull*)&ts[4096 + o + 2];
#pragma unroll 16
            for (int j = 0; j < 64; j++) {
                ull h2 = hd[q][j];
                ulonglong2 t4 = ts2[j * 16 + l16];
                acc0 = ffma2(h2, t4.x, acc0);
                acc1 = ffma2(h2, t4.y, acc1);
            }
            int dst = dsts[q];
            float* sp = g_sums + dst * 64 + o;
            atomicAdd(sp + 0, __uint_as_float((unsigned)acc0));
            atomicAdd(sp + 1, __uint_as_float((unsigned)(acc0 >> 32)));
            atomicAdd(sp + 2, __uint_as_float((unsigned)acc1));
            atomicAdd(sp + 3, __uint_as_float((unsigned)(acc1 >> 32)));
        }
        __syncthreads();
    }
}

// ---------------- L5: scatter-mean + root + ReLU + 4 heads ----------------
__global__ void k_final(const float* __restrict__ root_w, const float* __restrict__ conv_b,
                        const float* __restrict__ wsu, const float* __restrict__ bsu,
                        const float* __restrict__ wnt, const float* __restrict__ bnt,
                        const float* __restrict__ wtg, const float* __restrict__ btg,
                        const float* __restrict__ wpr, const float* __restrict__ bpr,
                        float* __restrict__ out) {
    extern __shared__ float sm[];
    float* rw = sm;                  // 4096
    float* cb = rw + 4096;           // 64
    float* Wc = cb + 64;             // 64*240
    float* bc = Wc + 64 * 240;       // 240
    float* stage = bc + 240;         // 8 * 128
    int tid = threadIdx.x;
    for (int i = tid; i < 4096; i += 256) rw[i] = root_w[i];
    if (tid < 64) cb[tid] = conv_b[tid];
    for (int i = tid; i < 64 * 16; i += 256)  { int r = i >> 4, c = i & 15;  Wc[r * 240 + c]       = wsu[i]; }
    for (int i = tid; i < 64 * 32; i += 256)  { int r = i >> 5, c = i & 31;  Wc[r * 240 + 16 + c]  = wnt[i]; }
    for (int i = tid; i < 64 * 64; i += 256)  { int r = i >> 6, c = i & 63;  Wc[r * 240 + 48 + c]  = wtg[i]; }
    for (int i = tid; i < 64 * 128; i += 256) { int r = i >> 7, c = i & 127; Wc[r * 240 + 112 + c] = wpr[i]; }
    if (tid < 16)       bc[tid] = bsu[tid];
    else if (tid < 48)  bc[tid] = bnt[tid - 16];
    else if (tid < 112) bc[tid] = btg[tid - 48];
    else if (tid < 240) bc[tid] = bpr[tid - 112];
    __syncthreads();

    int w = tid >> 5, l = tid & 31;
    int n = blockIdx.x * 8 + w;
    if (n >= NN) return;
    float* xs = stage + w * 128;
    float* os = xs + 64;
    xs[l] = g_xf[n * 64 + l];
    xs[l + 32] = g_xf[n * 64 + 32 + l];
    __syncwarp();

    float inv = 1.f / fmaxf((float)g_dcnt[n], 1.f);
#pragma unroll
    for (int half = 0; half < 2; half++) {
        int o = l + 32 * half;
        float acc = cb[o] + g_sums[n * 64 + o] * inv;
#pragma unroll 8
        for (int i = 0; i < 64; i++) acc = fmaf(xs[i], rw[i * 64 + o], acc);
        os[o] = fmaxf(acc, 0.f);
    }
    __syncwarp();

#pragma unroll
    for (int q = 0; q < 8; q++) {
        int t = l + 32 * q;
        if (t < 240) {
            float acc = bc[t];
#pragma unroll 8
            for (int i = 0; i < 64; i++) acc = fmaf(os[i], Wc[i * 240 + t], acc);
            if (t < 16)       out[n * 16 + t] = acc;
            else if (t < 48)  out[240000  + n * 32  + (t - 16)]  = acc;
            else if (t < 112) out[720000  + n * 64  + (t - 48)]  = acc;
            else              out[1680000 + n * 128 + (t - 112)] = acc;
        }
    }
}

// ---------------- launch ----------------
extern "C" void kernel_launch(void* const* d_in, const int* in_sizes, int n_in,
                              void* d_out, int out_size) {
    const float* x        = (const float*)d_in[0];
    const int*   input_np = (const int*)  d_in[1];
    const int*   output_np= (const int*)  d_in[2];
    const int*   edge_idx = (const int*)  d_in[3];
    const int*   edge_nt  = (const int*)  d_in[4];
    const int*   edge_np  = (const int*)  d_in[5];
    const float* edge_sc  = (const float*)d_in[6];
    const float* in_emb   = (const float*)d_in[7];
    const float* out_emb  = (const float*)d_in[8];
    const float* enp_emb  = (const float*)d_in[9];
    const float* ent_emb  = (const float*)d_in[10];
    const float* w1       = (const float*)d_in[11];
    const float* b1       = (const float*)d_in[12];
    const float* w2       = (const float*)d_in[13];
    const float* b2       = (const float*)d_in[14];
    const float* root_w   = (const float*)d_in[15];
    const float* conv_b   = (const float*)d_in[16];
    const float* wsu      = (const float*)d_in[17];
    const float* bsu      = (const float*)d_in[18];
    const float* wnt      = (const float*)d_in[19];
    const float* bnt      = (const float*)d_in[20];
    const float* wtg      = (const float*)d_in[21];
    const float* btg      = (const float*)d_in[22];
    const float* wpr      = (const float*)d_in[23];
    const float* bpr      = (const float*)d_in[24];
    float* out = (float*)d_out;

    const int smem_gemm  = (64 * 132 + 64 * 64) * 4;                       // 50176 B
    const int smem_final = (4096 + 64 + 64 * 240 + 240 + 8 * 128) * 4;     // 83136 B
    cudaFuncSetAttribute(k_gemm,  cudaFuncAttributeMaxDynamicSharedMemorySize, smem_gemm);
    cudaFuncSetAttribute(k_final, cudaFuncAttributeMaxDynamicSharedMemorySize, smem_final);

    k_init<<<(NN * HD + 255) / 256, 256>>>(w2, b2);                        // idx 0
    k_prep<<<NB_NODE + NB_HIST + NB_MLP, 256>>>(x, input_np, output_np,    // idx 1
            in_emb, out_emb, edge_idx, edge_nt, edge_np, edge_sc,
            ent_emb, enp_emb, w1, b1);
    k_scanscatter<<<1, 1024>>>(edge_idx);                                  // idx 2
    dim3 ggrid(CT / 64, (NN + 127) / 128);
    k_gemm<<<ggrid, 256, smem_gemm>>>();                                   // idx 3 (profiled)
    k_edge_apply<<<NN, 128>>>(edge_idx);                                   // idx 4
    k_final<<<(NN + 7) / 8, 256, smem_final>>>(root_w, conv_b,             // idx 5
            wsu, bsu, wnt, bnt, wtg, btg, wpr, bpr, out);
}

// round 6
// speedup vs baseline: 2.4946x; 1.1585x over previous
#include <cuda_runtime.h>

// ---------------- problem constants ----------------
#define NN 15000          // nodes
#define NE 60000          // edges
#define ND 64             // NODE_DIM
#define HD 64             // HID
#define ED 33             // EDGE_DIM
#define CT 4160           // 65*64 columns of M (j=0..63 from w2, j=64 = b2 row)

typedef unsigned long long ull;

__device__ __forceinline__ ull ffma2(ull a, ull b, ull c) {
    ull d;
    asm("fma.rn.f32x2 %0, %1, %2, %3;" : "=l"(d) : "l"(a), "l"(b), "l"(c));
    return d;
}
__device__ __forceinline__ ull dup2(float x) {
    ull d;
    asm("mov.b64 %0, {%1, %1};" : "=l"(d) : "f"(x));
    return d;
}

// ---------------- device scratch ----------------
// Zero-init at load; consumers restore zeros after use (graph-replay safe).
__device__ float g_xf[NN * ND];
__device__ float g_h[NE * HD];
__device__ float g_M[ND * CT];           // M[i][j*64+o] = w2[j, i*64+o]; row j=64 = b2
__device__ float g_T[(size_t)NN * CT];   // per-node tensor (249.6 MB)
__device__ float g_sums[NN * HD];        // zeroed by k_final after read
__device__ int   g_dcnt[NN];             // zeroed by k_final after read
__device__ int   g_hist[NN];             // zeroed by k_scanscatter after read
__device__ int   g_off[NN + 1];
__device__ int   g_cursor[NN];
__device__ int   g_sorted[NE];

// ---------------- L0: M build + node features + degree hists + edge MLP ----------------
#define NB_M    1040     // ND*CT / 256
#define NB_NODE 1875
#define NB_HIST 235
#define NB_MLP  7500
__global__ void k_prep(const float* __restrict__ x,
                       const int* __restrict__ inp, const int* __restrict__ outp,
                       const float* __restrict__ in_emb, const float* __restrict__ out_emb,
                       const int* __restrict__ eidx,
                       const int* __restrict__ e_nt, const int* __restrict__ e_np,
                       const float* __restrict__ e_sc,
                       const float* __restrict__ nt_emb, const float* __restrict__ np_emb,
                       const float* __restrict__ w1, const float* __restrict__ b1,
                       const float* __restrict__ w2, const float* __restrict__ b2) {
    int b = blockIdx.x;
    int tid = threadIdx.x;
    if (b < NB_M) {                          // build M
        int idx = b * 256 + tid;
        if (idx >= ND * CT) return;
        int i = idx / CT;
        int col = idx - i * CT;
        int j = col >> 6;
        int o = col & 63;
        g_M[idx] = (j < 64) ? w2[j * 4096 + i * 64 + o] : b2[i * 64 + o];
        return;
    }
    if (b < NB_M + NB_NODE) {                // node features
        int w = tid >> 5, l = tid & 31;
        int n = (b - NB_M) * 8 + w;
        if (n >= NN) return;
        float v0 = x[n * 32 + l];
        float v1 = (l < 16) ? in_emb[inp[n] * 16 + l]
                            : out_emb[outp[n] * 16 + (l - 16)];
        g_xf[n * 64 + l] = v0;
        g_xf[n * 64 + 32 + l] = v1;
        return;
    }
    if (b < NB_M + NB_NODE + NB_HIST) {      // degree histograms (globals pre-zeroed)
        int e = (b - NB_M - NB_NODE) * 256 + tid;
        if (e >= NE) return;
        atomicAdd(&g_hist[eidx[e]], 1);
        atomicAdd(&g_dcnt[eidx[NE + e]], 1);
        return;
    }
    // edge MLP: h = relu(ea @ w1 + b1), 1 warp / edge
    __shared__ float w1s[ED * 64];
    __shared__ float b1s[64];
    __shared__ float eas[8][34];
    for (int i = tid; i < ED * 64; i += 256) w1s[i] = w1[i];
    if (tid < 64) b1s[tid] = b1[tid];
    __syncthreads();
    int w = tid >> 5, l = tid & 31;
    int e = (b - NB_M - NB_NODE - NB_HIST) * 8 + w;
    if (e >= NE) return;
    if (l < 16) eas[w][l] = nt_emb[e_nt[e] * 16 + l];
    else        eas[w][l] = np_emb[e_np[e] * 16 + (l - 16)];
    if (l == 0) eas[w][32] = e_sc[e];
    __syncwarp();
    int o0 = l, o1 = l + 32;
    float a0 = b1s[o0], a1 = b1s[o1];
#pragma unroll
    for (int k = 0; k < ED; k++) {
        float v = eas[w][k];
        a0 = fmaf(v, w1s[k * 64 + o0], a0);
        a1 = fmaf(v, w1s[k * 64 + o1], a1);
    }
    g_h[e * 64 + o0] = fmaxf(a0, 0.f);
    g_h[e * 64 + o1] = fmaxf(a1, 0.f);
}

// ---------------- L1: CSR scan + scatter (single block); zeroes g_hist ----------------
__global__ void k_scanscatter(const int* __restrict__ eidx) {
    __shared__ int warp_sums[32];
    __shared__ int s_carry;
    int tid = threadIdx.x;
    int lane = tid & 31, wid = tid >> 5;
    if (tid == 0) { s_carry = 0; g_off[0] = 0; }
    __syncthreads();
    for (int base = 0; base < NN; base += 1024) {
        int i = base + tid;
        int v = (i < NN) ? g_hist[i] : 0;
        if (i < NN) g_hist[i] = 0;          // restore zero for next replay
        int xv = v;
#pragma unroll
        for (int d = 1; d < 32; d <<= 1) {
            int y = __shfl_up_sync(0xffffffffu, xv, d);
            if (lane >= d) xv += y;
        }
        if (lane == 31) warp_sums[wid] = xv;
        __syncthreads();
        if (tid < 32) {
            int w = warp_sums[tid];
#pragma unroll
            for (int d = 1; d < 32; d <<= 1) {
                int y = __shfl_up_sync(0xffffffffu, w, d);
                if (tid >= d) w += y;
            }
            warp_sums[tid] = w;
        }
        __syncthreads();
        int incl = xv + ((wid > 0) ? warp_sums[wid - 1] : 0) + s_carry;
        if (i < NN) { g_off[i + 1] = incl; g_cursor[i] = incl - v; }
        __syncthreads();
        if (tid == 0) s_carry += warp_sums[31];
        __syncthreads();
    }
    for (int e = tid; e < NE; e += 1024) {
        int pos = atomicAdd(&g_cursor[eidx[e]], 1);
        g_sorted[pos] = e;
    }
}

// ---------------- L2: GEMM  T[NN, CT] = g_xf[NN,64] @ g_M[64, CT] ----------------
// Round-3 config: tile 256m x 64n, K=64, 256 threads, 8x8 per thread via FFMA2.
__global__ __launch_bounds__(256) void k_gemm() {
    extern __shared__ float sm[];
    float* At = sm;              // [64][260]  (k-major, padded)
    float* Bs = sm + 64 * 260;   // [64][64]
    int tid = threadIdx.x;
    int c0 = blockIdx.x * 64;
    int r0 = blockIdx.y * 256;

    {
        int row = r0 + tid;
        if (row < NN) {
            const float4* ap = (const float4*)(g_xf + row * 64);
#pragma unroll
            for (int q = 0; q < 16; q++) {
                float4 v = ap[q];
                At[(4 * q + 0) * 260 + tid] = v.x;
                At[(4 * q + 1) * 260 + tid] = v.y;
                At[(4 * q + 2) * 260 + tid] = v.z;
                At[(4 * q + 3) * 260 + tid] = v.w;
            }
        } else {
#pragma unroll
            for (int k = 0; k < 64; k++) At[k * 260 + tid] = 0.f;
        }
    }
#pragma unroll
    for (int q = 0; q < 4; q++) {
        int idx = q * 256 + tid;          // float4 index, 1024 total
        int k = idx >> 4;
        int c = idx & 15;
        ((float4*)Bs)[k * 16 + c] = *(const float4*)&g_M[k * CT + c0 + c * 4];
    }
    __syncthreads();

    int m0 = (tid >> 3) * 8;   // 32 m-groups -> 256 rows
    int n0 = (tid & 7) * 8;    // 8 n-groups  -> 64 cols
    ull acc[8][4];
#pragma unroll
    for (int i = 0; i < 8; i++)
#pragma unroll
        for (int j = 0; j < 4; j++) acc[i][j] = 0ull;

#pragma unroll 4
    for (int k = 0; k < 64; k++) {
        float4 a0 = *(const float4*)&At[k * 260 + m0];
        float4 a1 = *(const float4*)&At[k * 260 + m0 + 4];
        ulonglong2 b0 = *(const ulonglong2*)&Bs[k * 64 + n0];
        ulonglong2 b1 = *(const ulonglong2*)&Bs[k * 64 + n0 + 4];
        ull ad[8] = {dup2(a0.x), dup2(a0.y), dup2(a0.z), dup2(a0.w),
                     dup2(a1.x), dup2(a1.y), dup2(a1.z), dup2(a1.w)};
        ull bp[4] = {b0.x, b0.y, b1.x, b1.y};
#pragma unroll
        for (int i = 0; i < 8; i++)
#pragma unroll
            for (int j = 0; j < 4; j++)
                acc[i][j] = ffma2(ad[i], bp[j], acc[i][j]);
    }
#pragma unroll
    for (int i = 0; i < 8; i++) {
        int row = r0 + m0 + i;
        if (row < NN) {
            ulonglong2* dp = (ulonglong2*)(g_T + (size_t)row * CT + c0 + n0);
            dp[0] = make_ulonglong2(acc[i][0], acc[i][1]);
            dp[1] = make_ulonglong2(acc[i][2], acc[i][3]);
        }
    }
}

// ---------------- L3: per-src-node edge apply (1 block / node, T row in smem) ----------------
__global__ void k_edge_apply(const int* __restrict__ eidx) {
    __shared__ __align__(16) float ts[CT];     // 16640 B (T row for this src)
    __shared__ ull hd[8][64];                  // 4096 B (packed dup h per edge)
    __shared__ int dsts[8];
    int n = blockIdx.x;
    int beg = g_off[n], end = g_off[n + 1];
    if (beg == end) return;
    int tid = threadIdx.x;                     // 128 threads
    const float4* Tp = (const float4*)(g_T + (size_t)n * CT);
    float4* tsp = (float4*)ts;
    for (int i = tid; i < CT / 4; i += 128) tsp[i] = Tp[i];
    __syncthreads();

    int q = tid >> 4;          // edge slot 0..7
    int l16 = tid & 15;
    int o = l16 * 4;           // 4 outputs o..o+3
    const ulonglong2* ts2 = (const ulonglong2*)ts;

    for (int p = beg; p < end; p += 8) {
        int idx = p + q;
        int e = -1;
        if (idx < end) {
            e = g_sorted[idx];
            const float* hp = g_h + e * 64;
#pragma unroll
            for (int t = 0; t < 4; t++) hd[q][o + t] = dup2(hp[o + t]);
            if (l16 == 0) dsts[q] = eidx[NE + e];
        }
        __syncthreads();
        if (e >= 0) {
            ull acc0 = *(const ull*)&ts[4096 + o];      // b2 row (h'[64]=1)
            ull acc1 = *(const ull*)&ts[4096 + o + 2];
#pragma unroll 16
            for (int j = 0; j < 64; j++) {
                ull h2 = hd[q][j];
                ulonglong2 t4 = ts2[j * 16 + l16];
                acc0 = ffma2(h2, t4.x, acc0);
                acc1 = ffma2(h2, t4.y, acc1);
            }
            int dst = dsts[q];
            float* sp = g_sums + dst * 64 + o;
            atomicAdd(sp + 0, __uint_as_float((unsigned)acc0));
            atomicAdd(sp + 1, __uint_as_float((unsigned)(acc0 >> 32)));
            atomicAdd(sp + 2, __uint_as_float((unsigned)acc1));
            atomicAdd(sp + 3, __uint_as_float((unsigned)(acc1 >> 32)));
        }
        __syncthreads();
    }
}

// ---------------- L4: scatter-mean + root + ReLU + 4 heads; restores zeros ----------------
__global__ void k_final(const float* __restrict__ root_w, const float* __restrict__ conv_b,
                        const float* __restrict__ wsu, const float* __restrict__ bsu,
                        const float* __restrict__ wnt, const float* __restrict__ bnt,
                        const float* __restrict__ wtg, const float* __restrict__ btg,
                        const float* __restrict__ wpr, const float* __restrict__ bpr,
                        float* __restrict__ out) {
    extern __shared__ float sm[];
    float* rw = sm;                  // 4096
    float* cb = rw + 4096;           // 64
    float* Wc = cb + 64;             // 64*240
    float* bc = Wc + 64 * 240;       // 240
    float* stage = bc + 240;         // 8 * 128
    int tid = threadIdx.x;
    for (int i = tid; i < 4096; i += 256) rw[i] = root_w[i];
    if (tid < 64) cb[tid] = conv_b[tid];
    for (int i = tid; i < 64 * 16; i += 256)  { int r = i >> 4, c = i & 15;  Wc[r * 240 + c]       = wsu[i]; }
    for (int i = tid; i < 64 * 32; i += 256)  { int r = i >> 5, c = i & 31;  Wc[r * 240 + 16 + c]  = wnt[i]; }
    for (int i = tid; i < 64 * 64; i += 256)  { int r = i >> 6, c = i & 63;  Wc[r * 240 + 48 + c]  = wtg[i]; }
    for (int i = tid; i < 64 * 128; i += 256) { int r = i >> 7, c = i & 127; Wc[r * 240 + 112 + c] = wpr[i]; }
    if (tid < 16)       bc[tid] = bsu[tid];
    else if (tid < 48)  bc[tid] = bnt[tid - 16];
    else if (tid < 112) bc[tid] = btg[tid - 48];
    else if (tid < 240) bc[tid] = bpr[tid - 112];
    __syncthreads();

    int w = tid >> 5, l = tid & 31;
    int n = blockIdx.x * 8 + w;
    if (n >= NN) return;
    float* xs = stage + w * 128;
    float* os = xs + 64;
    xs[l] = g_xf[n * 64 + l];
    xs[l + 32] = g_xf[n * 64 + 32 + l];
    __syncwarp();

    float inv = 1.f / fmaxf((float)g_dcnt[n], 1.f);
    if (l == 0) g_dcnt[n] = 0;                          // restore zero
#pragma unroll
    for (int half = 0; half < 2; half++) {
        int o = l + 32 * half;
        float sv = g_sums[n * 64 + o];
        g_sums[n * 64 + o] = 0.f;                       // restore zero
        float acc = cb[o] + sv * inv;
#pragma unroll 8
        for (int i = 0; i < 64; i++) acc = fmaf(xs[i], rw[i * 64 + o], acc);
        os[o] = fmaxf(acc, 0.f);
    }
    __syncwarp();

#pragma unroll
    for (int q = 0; q < 8; q++) {
        int t = l + 32 * q;
        if (t < 240) {
            float acc = bc[t];
#pragma unroll 8
            for (int i = 0; i < 64; i++) acc = fmaf(os[i], Wc[i * 240 + t], acc);
            if (t < 16)       out[n * 16 + t] = acc;
            else if (t < 48)  out[240000  + n * 32  + (t - 16)]  = acc;
            else if (t < 112) out[720000  + n * 64  + (t - 48)]  = acc;
            else              out[1680000 + n * 128 + (t - 112)] = acc;
        }
    }
}

// ---------------- launch ----------------
extern "C" void kernel_launch(void* const* d_in, const int* in_sizes, int n_in,
                              void* d_out, int out_size) {
    const float* x        = (const float*)d_in[0];
    const int*   input_np = (const int*)  d_in[1];
    const int*   output_np= (const int*)  d_in[2];
    const int*   edge_idx = (const int*)  d_in[3];
    const int*   edge_nt  = (const int*)  d_in[4];
    const int*   edge_np  = (const int*)  d_in[5];
    const float* edge_sc  = (const float*)d_in[6];
    const float* in_emb   = (const float*)d_in[7];
    const float* out_emb  = (const float*)d_in[8];
    const float* enp_emb  = (const float*)d_in[9];
    const float* ent_emb  = (const float*)d_in[10];
    const float* w1       = (const float*)d_in[11];
    const float* b1       = (const float*)d_in[12];
    const float* w2       = (const float*)d_in[13];
    const float* b2       = (const float*)d_in[14];
    const float* root_w   = (const float*)d_in[15];
    const float* conv_b   = (const float*)d_in[16];
    const float* wsu      = (const float*)d_in[17];
    const float* bsu      = (const float*)d_in[18];
    const float* wnt      = (const float*)d_in[19];
    const float* bnt      = (const float*)d_in[20];
    const float* wtg      = (const float*)d_in[21];
    const float* btg      = (const float*)d_in[22];
    const float* wpr      = (const float*)d_in[23];
    const float* bpr      = (const float*)d_in[24];
    float* out = (float*)d_out;

    const int smem_gemm  = (64 * 260 + 64 * 64) * 4;                       // 82944 B
    const int smem_final = (4096 + 64 + 64 * 240 + 240 + 8 * 128) * 4;     // 83136 B
    cudaFuncSetAttribute(k_gemm,  cudaFuncAttributeMaxDynamicSharedMemorySize, smem_gemm);
    cudaFuncSetAttribute(k_final, cudaFuncAttributeMaxDynamicSharedMemorySize, smem_final);

    k_prep<<<NB_M + NB_NODE + NB_HIST + NB_MLP, 256>>>(x, input_np, output_np,  // idx 0
            in_emb, out_emb, edge_idx, edge_nt, edge_np, edge_sc,
            ent_emb, enp_emb, w1, b1, w2, b2);
    k_scanscatter<<<1, 1024>>>(edge_idx);                                  // idx 1
    dim3 ggrid(CT / 64, (NN + 255) / 256);
    k_gemm<<<ggrid, 256, smem_gemm>>>();                                   // idx 2
    k_edge_apply<<<NN, 128>>>(edge_idx);                                   // idx 3 (profiled)
    k_final<<<(NN + 7) / 8, 256, smem_final>>>(root_w, conv_b,             // idx 4
            wsu, bsu, wnt, bnt, wtg, btg, wpr, bpr, out);
}

// round 7
// speedup vs baseline: 2.7444x; 1.1002x over previous
#include <cuda_runtime.h>

// ---------------- problem constants ----------------
#define NN 15000          // nodes
#define NE 60000          // edges
#define ND 64             // NODE_DIM
#define HD 64             // HID
#define ED 33             // EDGE_DIM
#define CT 4160           // 65*64 columns of M (j=0..63 from w2, j=64 = b2 row)

typedef unsigned long long ull;

__device__ __forceinline__ ull ffma2(ull a, ull b, ull c) {
    ull d;
    asm("fma.rn.f32x2 %0, %1, %2, %3;" : "=l"(d) : "l"(a), "l"(b), "l"(c));
    return d;
}
__device__ __forceinline__ ull dup2(float x) {
    ull d;
    asm("mov.b64 %0, {%1, %1};" : "=l"(d) : "f"(x));
    return d;
}

// ---------------- device scratch ----------------
// Zero-init at load; consumers restore zeros after use (graph-replay safe).
__device__ float g_xf[NN * ND];
__device__ float g_h[NE * HD];
__device__ float g_M[ND * CT];           // M[i][j*64+o] = w2[j, i*64+o]; row j=64 = b2
__device__ float g_T[(size_t)NN * CT];   // per-node tensor (249.6 MB)
__device__ float g_sums[NN * HD];        // zeroed by k_final after read
__device__ int   g_dcnt[NN];             // zeroed by k_final after read
__device__ int   g_hist[NN];             // zeroed by k_scanscatter after read
__device__ int   g_off[NN + 1];
__device__ int   g_cursor[NN];
__device__ int   g_sorted[NE];

// ---------------- L0: M build + node features + degree hists ----------------
#define NB_M    1040     // ND*CT / 256
#define NB_NODE 1875
#define NB_HIST 235
__global__ void k_prepA(const float* __restrict__ x,
                        const int* __restrict__ inp, const int* __restrict__ outp,
                        const float* __restrict__ in_emb, const float* __restrict__ out_emb,
                        const int* __restrict__ eidx,
                        const float* __restrict__ w2, const float* __restrict__ b2) {
    int b = blockIdx.x;
    int tid = threadIdx.x;
    if (b < NB_M) {                          // build M
        int idx = b * 256 + tid;
        if (idx >= ND * CT) return;
        int i = idx / CT;
        int col = idx - i * CT;
        int j = col >> 6;
        int o = col & 63;
        g_M[idx] = (j < 64) ? w2[j * 4096 + i * 64 + o] : b2[i * 64 + o];
        return;
    }
    if (b < NB_M + NB_NODE) {                // node features
        int w = tid >> 5, l = tid & 31;
        int n = (b - NB_M) * 8 + w;
        if (n >= NN) return;
        float v0 = x[n * 32 + l];
        float v1 = (l < 16) ? in_emb[inp[n] * 16 + l]
                            : out_emb[outp[n] * 16 + (l - 16)];
        g_xf[n * 64 + l] = v0;
        g_xf[n * 64 + 32 + l] = v1;
        return;
    }
    // degree histograms (globals pre-zeroed / restored each run)
    int e = (b - NB_M - NB_NODE) * 256 + tid;
    if (e >= NE) return;
    atomicAdd(&g_hist[eidx[e]], 1);
    atomicAdd(&g_dcnt[eidx[NE + e]], 1);
}

// ---------------- L1: edge MLP h = relu(ea @ w1 + b1), 32 edges / block ----------------
__global__ void k_prepB(const int* __restrict__ e_nt, const int* __restrict__ e_np,
                        const float* __restrict__ e_sc,
                        const float* __restrict__ nt_emb, const float* __restrict__ np_emb,
                        const float* __restrict__ w1, const float* __restrict__ b1) {
    __shared__ float w1s[ED * 64];
    __shared__ float b1s[64];
    __shared__ float eas[8][34];
    int tid = threadIdx.x;
    for (int i = tid; i < ED * 64; i += 256) w1s[i] = w1[i];
    if (tid < 64) b1s[tid] = b1[tid];
    __syncthreads();
    int w = tid >> 5, l = tid & 31;
#pragma unroll
    for (int pass = 0; pass < 4; pass++) {
        int e = (blockIdx.x * 4 + pass) * 8 + w;
        if (e >= NE) break;
        if (l < 16) eas[w][l] = nt_emb[e_nt[e] * 16 + l];
        else        eas[w][l] = np_emb[e_np[e] * 16 + (l - 16)];
        if (l == 0) eas[w][32] = e_sc[e];
        __syncwarp();
        int o0 = l, o1 = l + 32;
        float a0 = b1s[o0], a1 = b1s[o1];
#pragma unroll
        for (int k = 0; k < ED; k++) {
            float v = eas[w][k];
            a0 = fmaf(v, w1s[k * 64 + o0], a0);
            a1 = fmaf(v, w1s[k * 64 + o1], a1);
        }
        g_h[e * 64 + o0] = fmaxf(a0, 0.f);
        g_h[e * 64 + o1] = fmaxf(a1, 0.f);
        __syncwarp();
    }
}

// ---------------- L2: CSR scan + scatter (single block); zeroes g_hist ----------------
__global__ void k_scanscatter(const int* __restrict__ eidx) {
    __shared__ int warp_sums[32];
    __shared__ int s_carry;
    int tid = threadIdx.x;
    int lane = tid & 31, wid = tid >> 5;
    if (tid == 0) { s_carry = 0; g_off[0] = 0; }
    __syncthreads();
    for (int base = 0; base < NN; base += 1024) {
        int i = base + tid;
        int v = (i < NN) ? g_hist[i] : 0;
        if (i < NN) g_hist[i] = 0;          // restore zero for next replay
        int xv = v;
#pragma unroll
        for (int d = 1; d < 32; d <<= 1) {
            int y = __shfl_up_sync(0xffffffffu, xv, d);
            if (lane >= d) xv += y;
        }
        if (lane == 31) warp_sums[wid] = xv;
        __syncthreads();
        if (tid < 32) {
            int w = warp_sums[tid];
#pragma unroll
            for (int d = 1; d < 32; d <<= 1) {
                int y = __shfl_up_sync(0xffffffffu, w, d);
                if (tid >= d) w += y;
            }
            warp_sums[tid] = w;
        }
        __syncthreads();
        int incl = xv + ((wid > 0) ? warp_sums[wid - 1] : 0) + s_carry;
        if (i < NN) { g_off[i + 1] = incl; g_cursor[i] = incl - v; }
        __syncthreads();
        if (tid == 0) s_carry += warp_sums[31];
        __syncthreads();
    }
    for (int e = tid; e < NE; e += 1024) {
        int pos = atomicAdd(&g_cursor[eidx[e]], 1);
        g_sorted[pos] = e;
    }
}

// ---------------- L3 (PROFILED): GEMM  T = g_xf[NN,64] @ g_M[64,CT] ----------------
// Tile 256m x 64n, K=64, 256 threads, 8x8 per thread via FFMA2.
__global__ __launch_bounds__(256) void k_gemm() {
    extern __shared__ float sm[];
    float* At = sm;              // [64][260]  (k-major, padded)
    float* Bs = sm + 64 * 260;   // [64][64]
    int tid = threadIdx.x;
    int c0 = blockIdx.x * 64;
    int r0 = blockIdx.y * 256;

    {
        int row = r0 + tid;
        if (row < NN) {
            const float4* ap = (const float4*)(g_xf + row * 64);
#pragma unroll
            for (int q = 0; q < 16; q++) {
                float4 v = ap[q];
                At[(4 * q + 0) * 260 + tid] = v.x;
                At[(4 * q + 1) * 260 + tid] = v.y;
                At[(4 * q + 2) * 260 + tid] = v.z;
                At[(4 * q + 3) * 260 + tid] = v.w;
            }
        } else {
#pragma unroll
            for (int k = 0; k < 64; k++) At[k * 260 + tid] = 0.f;
        }
    }
#pragma unroll
    for (int q = 0; q < 4; q++) {
        int idx = q * 256 + tid;          // float4 index, 1024 total
        int k = idx >> 4;
        int c = idx & 15;
        ((float4*)Bs)[k * 16 + c] = *(const float4*)&g_M[k * CT + c0 + c * 4];
    }
    __syncthreads();

    int m0 = (tid >> 3) * 8;   // 32 m-groups -> 256 rows
    int n0 = (tid & 7) * 8;    // 8 n-groups  -> 64 cols
    ull acc[8][4];
#pragma unroll
    for (int i = 0; i < 8; i++)
#pragma unroll
        for (int j = 0; j < 4; j++) acc[i][j] = 0ull;

#pragma unroll 4
    for (int k = 0; k < 64; k++) {
        float4 a0 = *(const float4*)&At[k * 260 + m0];
        float4 a1 = *(const float4*)&At[k * 260 + m0 + 4];
        ulonglong2 b0 = *(const ulonglong2*)&Bs[k * 64 + n0];
        ulonglong2 b1 = *(const ulonglong2*)&Bs[k * 64 + n0 + 4];
        ull ad[8] = {dup2(a0.x), dup2(a0.y), dup2(a0.z), dup2(a0.w),
                     dup2(a1.x), dup2(a1.y), dup2(a1.z), dup2(a1.w)};
        ull bp[4] = {b0.x, b0.y, b1.x, b1.y};
#pragma unroll
        for (int i = 0; i < 8; i++)
#pragma unroll
            for (int j = 0; j < 4; j++)
                acc[i][j] = ffma2(ad[i], bp[j], acc[i][j]);
    }
#pragma unroll
    for (int i = 0; i < 8; i++) {
        int row = r0 + m0 + i;
        if (row < NN) {
            ulonglong2* dp = (ulonglong2*)(g_T + (size_t)row * CT + c0 + n0);
            dp[0] = make_ulonglong2(acc[i][0], acc[i][1]);
            dp[1] = make_ulonglong2(acc[i][2], acc[i][3]);
        }
    }
}

// ---------------- L4: per-src-node edge apply (1 block / node, T row in smem) ----------------
__global__ void k_edge_apply(const int* __restrict__ eidx) {
    __shared__ __align__(16) float ts[CT];     // 16640 B (T row for this src)
    __shared__ ull hd[8][64];                  // 4096 B (packed dup h per edge)
    __shared__ int dsts[8];
    int n = blockIdx.x;
    int beg = g_off[n], end = g_off[n + 1];
    if (beg == end) return;
    int tid = threadIdx.x;                     // 128 threads
    const float4* Tp = (const float4*)(g_T + (size_t)n * CT);
    float4* tsp = (float4*)ts;
    for (int i = tid; i < CT / 4; i += 128) tsp[i] = Tp[i];
    __syncthreads();

    int q = tid >> 4;          // edge slot 0..7
    int l16 = tid & 15;
    int o = l16 * 4;           // 4 outputs o..o+3
    const ulonglong2* ts2 = (const ulonglong2*)ts;

    for (int p = beg; p < end; p += 8) {
        int idx = p + q;
        int e = -1;
        if (idx < end) {
            e = g_sorted[idx];
            const float* hp = g_h + e * 64;
#pragma unroll
            for (int t = 0; t < 4; t++) hd[q][o + t] = dup2(hp[o + t]);
            if (l16 == 0) dsts[q] = eidx[NE + e];
        }
        __syncthreads();
        if (e >= 0) {
            ull acc0 = *(const ull*)&ts[4096 + o];      // b2 row (h'[64]=1)
            ull acc1 = *(const ull*)&ts[4096 + o + 2];
#pragma unroll 16
            for (int j = 0; j < 64; j++) {
                ull h2 = hd[q][j];
                ulonglong2 t4 = ts2[j * 16 + l16];
                acc0 = ffma2(h2, t4.x, acc0);
                acc1 = ffma2(h2, t4.y, acc1);
            }
            int dst = dsts[q];
            float* sp = g_sums + dst * 64 + o;
            atomicAdd(sp + 0, __uint_as_float((unsigned)acc0));
            atomicAdd(sp + 1, __uint_as_float((unsigned)(acc0 >> 32)));
            atomicAdd(sp + 2, __uint_as_float((unsigned)acc1));
            atomicAdd(sp + 3, __uint_as_float((unsigned)(acc1 >> 32)));
        }
        __syncthreads();
    }
}

// ---------------- L5: scatter-mean + root + ReLU + 4 heads; 64 nodes/block ----------------
__global__ void k_final(const float* __restrict__ root_w, const float* __restrict__ conv_b,
                        const float* __restrict__ wsu, const float* __restrict__ bsu,
                        const float* __restrict__ wnt, const float* __restrict__ bnt,
                        const float* __restrict__ wtg, const float* __restrict__ btg,
                        const float* __restrict__ wpr, const float* __restrict__ bpr,
                        float* __restrict__ out) {
    extern __shared__ float sm[];
    float* rw = sm;                  // 4096
    float* cb = rw + 4096;           // 64
    float* Wc = cb + 64;             // 64*240
    float* bc = Wc + 64 * 240;       // 240
    float* stage = bc + 240;         // 8 * 128
    int tid = threadIdx.x;
    for (int i = tid; i < 4096; i += 256) rw[i] = root_w[i];
    if (tid < 64) cb[tid] = conv_b[tid];
    for (int i = tid; i < 64 * 16; i += 256)  { int r = i >> 4, c = i & 15;  Wc[r * 240 + c]       = wsu[i]; }
    for (int i = tid; i < 64 * 32; i += 256)  { int r = i >> 5, c = i & 31;  Wc[r * 240 + 16 + c]  = wnt[i]; }
    for (int i = tid; i < 64 * 64; i += 256)  { int r = i >> 6, c = i & 63;  Wc[r * 240 + 48 + c]  = wtg[i]; }
    for (int i = tid; i < 64 * 128; i += 256) { int r = i >> 7, c = i & 127; Wc[r * 240 + 112 + c] = wpr[i]; }
    if (tid < 16)       bc[tid] = bsu[tid];
    else if (tid < 48)  bc[tid] = bnt[tid - 16];
    else if (tid < 112) bc[tid] = btg[tid - 48];
    else if (tid < 240) bc[tid] = bpr[tid - 112];
    __syncthreads();

    int w = tid >> 5, l = tid & 31;
    float* xs = stage + w * 128;
    float* os = xs + 64;

#pragma unroll
    for (int pass = 0; pass < 8; pass++) {
        int n = blockIdx.x * 64 + pass * 8 + w;
        if (n >= NN) break;
        xs[l] = g_xf[n * 64 + l];
        xs[l + 32] = g_xf[n * 64 + 32 + l];
        __syncwarp();

        float inv = 1.f / fmaxf((float)g_dcnt[n], 1.f);
        if (l == 0) g_dcnt[n] = 0;                          // restore zero
#pragma unroll
        for (int half = 0; half < 2; half++) {
            int o = l + 32 * half;
            float sv = g_sums[n * 64 + o];
            g_sums[n * 64 + o] = 0.f;                       // restore zero
            float acc = cb[o] + sv * inv;
#pragma unroll 8
            for (int i = 0; i < 64; i++) acc = fmaf(xs[i], rw[i * 64 + o], acc);
            os[o] = fmaxf(acc, 0.f);
        }
        __syncwarp();

#pragma unroll
        for (int q = 0; q < 8; q++) {
            int t = l + 32 * q;
            if (t < 240) {
                float acc = bc[t];
#pragma unroll 8
                for (int i = 0; i < 64; i++) acc = fmaf(os[i], Wc[i * 240 + t], acc);
                if (t < 16)       out[n * 16 + t] = acc;
                else if (t < 48)  out[240000  + n * 32  + (t - 16)]  = acc;
                else if (t < 112) out[720000  + n * 64  + (t - 48)]  = acc;
                else              out[1680000 + n * 128 + (t - 112)] = acc;
            }
        }
        __syncwarp();
    }
}

// ---------------- launch ----------------
extern "C" void kernel_launch(void* const* d_in, const int* in_sizes, int n_in,
                              void* d_out, int out_size) {
    const float* x        = (const float*)d_in[0];
    const int*   input_np = (const int*)  d_in[1];
    const int*   output_np= (const int*)  d_in[2];
    const int*   edge_idx = (const int*)  d_in[3];
    const int*   edge_nt  = (const int*)  d_in[4];
    const int*   edge_np  = (const int*)  d_in[5];
    const float* edge_sc  = (const float*)d_in[6];
    const float* in_emb   = (const float*)d_in[7];
    const float* out_emb  = (const float*)d_in[8];
    const float* enp_emb  = (const float*)d_in[9];
    const float* ent_emb  = (const float*)d_in[10];
    const float* w1       = (const float*)d_in[11];
    const float* b1       = (const float*)d_in[12];
    const float* w2       = (const float*)d_in[13];
    const float* b2       = (const float*)d_in[14];
    const float* root_w   = (const float*)d_in[15];
    const float* conv_b   = (const float*)d_in[16];
    const float* wsu      = (const float*)d_in[17];
    const float* bsu      = (const float*)d_in[18];
    const float* wnt      = (const float*)d_in[19];
    const float* bnt      = (const float*)d_in[20];
    const float* wtg      = (const float*)d_in[21];
    const float* btg      = (const float*)d_in[22];
    const float* wpr      = (const float*)d_in[23];
    const float* bpr      = (const float*)d_in[24];
    float* out = (float*)d_out;

    const int smem_gemm  = (64 * 260 + 64 * 64) * 4;                       // 82944 B
    const int smem_final = (4096 + 64 + 64 * 240 + 240 + 8 * 128) * 4;     // 83136 B
    cudaFuncSetAttribute(k_gemm,  cudaFuncAttributeMaxDynamicSharedMemorySize, smem_gemm);
    cudaFuncSetAttribute(k_final, cudaFuncAttributeMaxDynamicSharedMemorySize, smem_final);

    k_prepA<<<NB_M + NB_NODE + NB_HIST, 256>>>(x, input_np, output_np,     // idx 0
            in_emb, out_emb, edge_idx, w2, b2);
    k_prepB<<<(NE + 31) / 32, 256>>>(edge_nt, edge_np, edge_sc,            // idx 1
            ent_emb, enp_emb, w1, b1);
    k_scanscatter<<<1, 1024>>>(edge_idx);                                  // idx 2
    dim3 ggrid(CT / 64, (NN + 255) / 256);
    k_gemm<<<ggrid, 256, smem_gemm>>>();                                   // idx 3 (profiled)
    k_edge_apply<<<NN, 128>>>(edge_idx);                                   // idx 4
    k_final<<<(NN + 63) / 64, 256, smem_final>>>(root_w, conv_b,           // idx 5
            wsu, bsu, wnt, bnt, wtg, btg, wpr, bpr, out);
}

// round 9
// speedup vs baseline: 3.2056x; 1.1680x over previous
#include <cuda_runtime.h>
#include <cstdint>

// ---------------- problem constants ----------------
#define NN 15000          // nodes
#define NE 60000          // edges
#define ND 64             // NODE_DIM
#define HD 64             // HID
#define ED 33             // EDGE_DIM
#define CT 4160           // 65*64 columns of M (j=0..63 from w2, j=64 = b2 row)

typedef unsigned long long ull;

__device__ __forceinline__ ull ffma2(ull a, ull b, ull c) {
    ull d;
    asm("fma.rn.f32x2 %0, %1, %2, %3;" : "=l"(d) : "l"(a), "l"(b), "l"(c));
    return d;
}
__device__ __forceinline__ ull dup2(float x) {
    ull d;
    asm("mov.b64 %0, {%1, %1};" : "=l"(d) : "f"(x));
    return d;
}
// tf32 convert: destination must be a .b32 register (ptxas rejects .f32 dst)
__device__ __forceinline__ float to_tf32(float x) {
    uint32_t r;
    asm("cvt.rna.tf32.f32 %0, %1;" : "=r"(r) : "f"(x));
    return __uint_as_float(r);
}
__device__ __forceinline__ void mma_tf32(float* d, const float2 aLo, const float2 aHi,
                                         const float2 b) {
    asm("mma.sync.aligned.m16n8k8.row.col.f32.tf32.tf32.f32 "
        "{%0,%1,%2,%3}, {%4,%5,%6,%7}, {%8,%9}, {%0,%1,%2,%3};"
        : "+f"(d[0]), "+f"(d[1]), "+f"(d[2]), "+f"(d[3])
        : "r"(__float_as_uint(aLo.x)), "r"(__float_as_uint(aHi.x)),
          "r"(__float_as_uint(aLo.y)), "r"(__float_as_uint(aHi.y)),
          "r"(__float_as_uint(b.x)),  "r"(__float_as_uint(b.y)));
}

// ---------------- device scratch ----------------
// Zero-init at load; consumers restore zeros after use (graph-replay safe).
__device__ float g_xf[NN * ND];
__device__ float g_h[NE * HD];
__device__ float g_M[ND * CT];           // M[i][j*64+o] = w2[j, i*64+o]; row j=64 = b2
__device__ float g_T[(size_t)NN * CT];   // per-node tensor (249.6 MB)
__device__ float g_sums[NN * HD];        // zeroed by k_final after read
__device__ int   g_dcnt[NN];             // zeroed by k_final after read
__device__ int   g_hist[NN];             // zeroed by k_scanscatter after read
__device__ int   g_off[NN + 1];
__device__ int   g_cursor[NN];
__device__ int   g_sorted[NE];

// ---------------- L0: M build + node features + degree hists ----------------
#define NB_M    1040     // ND*CT / 256
#define NB_NODE 1875
#define NB_HIST 235
__global__ void k_prepA(const float* __restrict__ x,
                        const int* __restrict__ inp, const int* __restrict__ outp,
                        const float* __restrict__ in_emb, const float* __restrict__ out_emb,
                        const int* __restrict__ eidx,
                        const float* __restrict__ w2, const float* __restrict__ b2) {
    int b = blockIdx.x;
    int tid = threadIdx.x;
    if (b < NB_M) {                          // build M
        int idx = b * 256 + tid;
        if (idx >= ND * CT) return;
        int i = idx / CT;
        int col = idx - i * CT;
        int j = col >> 6;
        int o = col & 63;
        g_M[idx] = (j < 64) ? w2[j * 4096 + i * 64 + o] : b2[i * 64 + o];
        return;
    }
    if (b < NB_M + NB_NODE) {                // node features
        int w = tid >> 5, l = tid & 31;
        int n = (b - NB_M) * 8 + w;
        if (n >= NN) return;
        float v0 = x[n * 32 + l];
        float v1 = (l < 16) ? in_emb[inp[n] * 16 + l]
                            : out_emb[outp[n] * 16 + (l - 16)];
        g_xf[n * 64 + l] = v0;
        g_xf[n * 64 + 32 + l] = v1;
        return;
    }
    // degree histograms (globals pre-zeroed / restored each run)
    int e = (b - NB_M - NB_NODE) * 256 + tid;
    if (e >= NE) return;
    atomicAdd(&g_hist[eidx[e]], 1);
    atomicAdd(&g_dcnt[eidx[NE + e]], 1);
}

// ---------------- L1: edge MLP h = relu(ea @ w1 + b1), 32 edges / block ----------------
__global__ void k_prepB(const int* __restrict__ e_nt, const int* __restrict__ e_np,
                        const float* __restrict__ e_sc,
                        const float* __restrict__ nt_emb, const float* __restrict__ np_emb,
                        const float* __restrict__ w1, const float* __restrict__ b1) {
    __shared__ float w1s[ED * 64];
    __shared__ float b1s[64];
    __shared__ float eas[8][34];
    int tid = threadIdx.x;
    for (int i = tid; i < ED * 64; i += 256) w1s[i] = w1[i];
    if (tid < 64) b1s[tid] = b1[tid];
    __syncthreads();
    int w = tid >> 5, l = tid & 31;
#pragma unroll
    for (int pass = 0; pass < 4; pass++) {
        int e = (blockIdx.x * 4 + pass) * 8 + w;
        if (e >= NE) break;
        if (l < 16) eas[w][l] = nt_emb[e_nt[e] * 16 + l];
        else        eas[w][l] = np_emb[e_np[e] * 16 + (l - 16)];
        if (l == 0) eas[w][32] = e_sc[e];
        __syncwarp();
        int o0 = l, o1 = l + 32;
        float a0 = b1s[o0], a1 = b1s[o1];
#pragma unroll
        for (int k = 0; k < ED; k++) {
            float v = eas[w][k];
            a0 = fmaf(v, w1s[k * 64 + o0], a0);
            a1 = fmaf(v, w1s[k * 64 + o1], a1);
        }
        g_h[e * 64 + o0] = fmaxf(a0, 0.f);
        g_h[e * 64 + o1] = fmaxf(a1, 0.f);
        __syncwarp();
    }
}

// ---------------- L2: CSR scan + scatter (single block); zeroes g_hist ----------------
__global__ void k_scanscatter(const int* __restrict__ eidx) {
    __shared__ int warp_sums[32];
    __shared__ int s_carry;
    int tid = threadIdx.x;
    int lane = tid & 31, wid = tid >> 5;
    if (tid == 0) { s_carry = 0; g_off[0] = 0; }
    __syncthreads();
    for (int base = 0; base < NN; base += 1024) {
        int i = base + tid;
        int v = (i < NN) ? g_hist[i] : 0;
        if (i < NN) g_hist[i] = 0;          // restore zero for next replay
        int xv = v;
#pragma unroll
        for (int d = 1; d < 32; d <<= 1) {
            int y = __shfl_up_sync(0xffffffffu, xv, d);
            if (lane >= d) xv += y;
        }
        if (lane == 31) warp_sums[wid] = xv;
        __syncthreads();
        if (tid < 32) {
            int w = warp_sums[tid];
#pragma unroll
            for (int d = 1; d < 32; d <<= 1) {
                int y = __shfl_up_sync(0xffffffffu, w, d);
                if (tid >= d) w += y;
            }
            warp_sums[tid] = w;
        }
        __syncthreads();
        int incl = xv + ((wid > 0) ? warp_sums[wid - 1] : 0) + s_carry;
        if (i < NN) { g_off[i + 1] = incl; g_cursor[i] = incl - v; }
        __syncthreads();
        if (tid == 0) s_carry += warp_sums[31];
        __syncthreads();
    }
    for (int e = tid; e < NE; e += 1024) {
        int pos = atomicAdd(&g_cursor[eidx[e]], 1);
        g_sorted[pos] = e;
    }
}

// ---------------- L3 (PROFILED): tf32 tensor-core GEMM  T = g_xf @ g_M ----------------
// Block tile 128m x 64n, K=64. 256 threads = 8 warps as 4(m) x 2(n); warp tile 32x32.
// mma.sync.m16n8k8 tf32. Custom smem layouts give 1 LDS.64 per fragment:
//   As[kk][mt][r(16)][p(8)] where p = (kc&3)*2 + (kc>>2)  (column pairs c,c+4 adjacent)
//   Bs[kk][nt][n(8)][p(8)]  where p = (kc&3)*2 + (kc>>2)  (k pairs k,k+4 adjacent)
__global__ __launch_bounds__(256) void k_gemm() {
    extern __shared__ float sm[];
    float* As = sm;                 // 8*8*16*8 = 8192 floats (32 KB)
    float* Bs = sm + 8192;          // 8*8*8*8  = 4096 floats (16 KB)
    int tid = threadIdx.x;
    int c0 = blockIdx.x * 64;
    int r0 = blockIdx.y * 128;

    // stage A (convert to tf32)
    for (int idx = tid; idx < 128 * 64; idx += 256) {
        int m = idx >> 6, k = idx & 63;
        int row = r0 + m;
        float v = (row < NN) ? g_xf[row * 64 + k] : 0.f;
        int kk = k >> 3, kc = k & 7, mt = m >> 4, r = m & 15;
        As[((kk * 8 + mt) * 16 + r) * 8 + (kc & 3) * 2 + (kc >> 2)] = to_tf32(v);
    }
    // stage B
    for (int idx = tid; idx < 64 * 64; idx += 256) {
        int k = idx >> 6, n = idx & 63;
        float v = g_M[k * CT + c0 + n];
        int kk = k >> 3, kc = k & 7, nt = n >> 3, nn = n & 7;
        Bs[((kk * 8 + nt) * 8 + nn) * 8 + (kc & 3) * 2 + (kc >> 2)] = to_tf32(v);
    }
    __syncthreads();

    int warp = tid >> 5, lane = tid & 31;
    int wm = warp & 3;              // m group: 32 rows
    int wn = warp >> 2;             // n group: 32 cols
    int r = lane >> 2, c = lane & 3;

    float acc[2][4][4];
#pragma unroll
    for (int i = 0; i < 2; i++)
#pragma unroll
        for (int j = 0; j < 4; j++)
#pragma unroll
            for (int q = 0; q < 4; q++) acc[i][j][q] = 0.f;

#pragma unroll
    for (int kk = 0; kk < 8; kk++) {
        float2 aLo[2], aHi[2], bv[4];
#pragma unroll
        for (int i = 0; i < 2; i++) {
            int base = ((kk * 8 + (wm * 2 + i)) * 16) * 8;
            aLo[i] = *(const float2*)&As[base + r * 8 + c * 2];
            aHi[i] = *(const float2*)&As[base + (r + 8) * 8 + c * 2];
        }
#pragma unroll
        for (int j = 0; j < 4; j++) {
            int nt = wn * 4 + j;
            bv[j] = *(const float2*)&Bs[((kk * 8 + nt) * 8 + r) * 8 + c * 2];
        }
#pragma unroll
        for (int i = 0; i < 2; i++)
#pragma unroll
            for (int j = 0; j < 4; j++)
                mma_tf32(acc[i][j], aLo[i], aHi[i], bv[j]);
    }

    // epilogue: c0,c1 at (row, col..col+1), c2,c3 at (row+8, ...)
#pragma unroll
    for (int i = 0; i < 2; i++) {
        int rb = r0 + wm * 32 + i * 16 + r;
#pragma unroll
        for (int j = 0; j < 4; j++) {
            int col = c0 + wn * 32 + j * 8 + c * 2;
            if (rb < NN)
                *(float2*)&g_T[(size_t)rb * CT + col] = make_float2(acc[i][j][0], acc[i][j][1]);
            if (rb + 8 < NN)
                *(float2*)&g_T[(size_t)(rb + 8) * CT + col] = make_float2(acc[i][j][2], acc[i][j][3]);
        }
    }
}

// ---------------- L4: per-src-node edge apply (1 block / node, T row in smem) ----------------
__global__ void k_edge_apply(const int* __restrict__ eidx) {
    __shared__ __align__(16) float ts[CT];     // 16640 B (T row for this src)
    __shared__ ull hd[8][64];                  // 4096 B (packed dup h per edge)
    __shared__ int dsts[8];
    int n = blockIdx.x;
    int beg = g_off[n], end = g_off[n + 1];
    if (beg == end) return;
    int tid = threadIdx.x;                     // 128 threads
    const float4* Tp = (const float4*)(g_T + (size_t)n * CT);
    float4* tsp = (float4*)ts;
    for (int i = tid; i < CT / 4; i += 128) tsp[i] = Tp[i];
    __syncthreads();

    int q = tid >> 4;          // edge slot 0..7
    int l16 = tid & 15;
    int o = l16 * 4;           // 4 outputs o..o+3
    const ulonglong2* ts2 = (const ulonglong2*)ts;

    for (int p = beg; p < end; p += 8) {
        int idx = p + q;
        int e = -1;
        if (idx < end) {
            e = g_sorted[idx];
            const float* hp = g_h + e * 64;
#pragma unroll
            for (int t = 0; t < 4; t++) hd[q][o + t] = dup2(hp[o + t]);
            if (l16 == 0) dsts[q] = eidx[NE + e];
        }
        __syncthreads();
        if (e >= 0) {
            ull acc0 = *(const ull*)&ts[4096 + o];      // b2 row (h'[64]=1)
            ull acc1 = *(const ull*)&ts[4096 + o + 2];
#pragma unroll 16
            for (int j = 0; j < 64; j++) {
                ull h2 = hd[q][j];
                ulonglong2 t4 = ts2[j * 16 + l16];
                acc0 = ffma2(h2, t4.x, acc0);
                acc1 = ffma2(h2, t4.y, acc1);
            }
            int dst = dsts[q];
            float* sp = g_sums + dst * 64 + o;
            atomicAdd(sp + 0, __uint_as_float((unsigned)acc0));
            atomicAdd(sp + 1, __uint_as_float((unsigned)(acc0 >> 32)));
            atomicAdd(sp + 2, __uint_as_float((unsigned)acc1));
            atomicAdd(sp + 3, __uint_as_float((unsigned)(acc1 >> 32)));
        }
        __syncthreads();
    }
}

// ---------------- L5: scatter-mean + root + ReLU + 4 heads; 64 nodes/block ----------------
__global__ void k_final(const float* __restrict__ root_w, const float* __restrict__ conv_b,
                        const float* __restrict__ wsu, const float* __restrict__ bsu,
                        const float* __restrict__ wnt, const float* __restrict__ bnt,
                        const float* __restrict__ wtg, const float* __restrict__ btg,
                        const float* __restrict__ wpr, const float* __restrict__ bpr,
                        float* __restrict__ out) {
    extern __shared__ float sm[];
    float* rw = sm;                  // 4096
    float* cb = rw + 4096;           // 64
    float* Wc = cb + 64;             // 64*240
    float* bc = Wc + 64 * 240;       // 240
    float* stage = bc + 240;         // 8 * 128
    int tid = threadIdx.x;
    for (int i = tid; i < 4096; i += 256) rw[i] = root_w[i];
    if (tid < 64) cb[tid] = conv_b[tid];
    for (int i = tid; i < 64 * 16; i += 256)  { int r = i >> 4, c = i & 15;  Wc[r * 240 + c]       = wsu[i]; }
    for (int i = tid; i < 64 * 32; i += 256)  { int r = i >> 5, c = i & 31;  Wc[r * 240 + 16 + c]  = wnt[i]; }
    for (int i = tid; i < 64 * 64; i += 256)  { int r = i >> 6, c = i & 63;  Wc[r * 240 + 48 + c]  = wtg[i]; }
    for (int i = tid; i < 64 * 128; i += 256) { int r = i >> 7, c = i & 127; Wc[r * 240 + 112 + c] = wpr[i]; }
    if (tid < 16)       bc[tid] = bsu[tid];
    else if (tid < 48)  bc[tid] = bnt[tid - 16];
    else if (tid < 112) bc[tid] = btg[tid - 48];
    else if (tid < 240) bc[tid] = bpr[tid - 112];
    __syncthreads();

    int w = tid >> 5, l = tid & 31;
    float* xs = stage + w * 128;
    float* os = xs + 64;

#pragma unroll
    for (int pass = 0; pass < 8; pass++) {
        int n = blockIdx.x * 64 + pass * 8 + w;
        if (n >= NN) break;
        xs[l] = g_xf[n * 64 + l];
        xs[l + 32] = g_xf[n * 64 + 32 + l];
        __syncwarp();

        float inv = 1.f / fmaxf((float)g_dcnt[n], 1.f);
        if (l == 0) g_dcnt[n] = 0;                          // restore zero
#pragma unroll
        for (int half = 0; half < 2; half++) {
            int o = l + 32 * half;
            float sv = g_sums[n * 64 + o];
            g_sums[n * 64 + o] = 0.f;                       // restore zero
            float acc = cb[o] + sv * inv;
#pragma unroll 8
            for (int i = 0; i < 64; i++) acc = fmaf(xs[i], rw[i * 64 + o], acc);
            os[o] = fmaxf(acc, 0.f);
        }
        __syncwarp();

#pragma unroll
        for (int q = 0; q < 8; q++) {
            int t = l + 32 * q;
            if (t < 240) {
                float acc = bc[t];
#pragma unroll 8
                for (int i = 0; i < 64; i++) acc = fmaf(os[i], Wc[i * 240 + t], acc);
                if (t < 16)       out[n * 16 + t] = acc;
                else if (t < 48)  out[240000  + n * 32  + (t - 16)]  = acc;
                else if (t < 112) out[720000  + n * 64  + (t - 48)]  = acc;
                else              out[1680000 + n * 128 + (t - 112)] = acc;
            }
        }
        __syncwarp();
    }
}

// ---------------- launch ----------------
extern "C" void kernel_launch(void* const* d_in, const int* in_sizes, int n_in,
                              void* d_out, int out_size) {
    const float* x        = (const float*)d_in[0];
    const int*   input_np = (const int*)  d_in[1];
    const int*   output_np= (const int*)  d_in[2];
    const int*   edge_idx = (const int*)  d_in[3];
    const int*   edge_nt  = (const int*)  d_in[4];
    const int*   edge_np  = (const int*)  d_in[5];
    const float* edge_sc  = (const float*)d_in[6];
    const float* in_emb   = (const float*)d_in[7];
    const float* out_emb  = (const float*)d_in[8];
    const float* enp_emb  = (const float*)d_in[9];
    const float* ent_emb  = (const float*)d_in[10];
    const float* w1       = (const float*)d_in[11];
    const float* b1       = (const float*)d_in[12];
    const float* w2       = (const float*)d_in[13];
    const float* b2       = (const float*)d_in[14];
    const float* root_w   = (const float*)d_in[15];
    const float* conv_b   = (const float*)d_in[16];
    const float* wsu      = (const float*)d_in[17];
    const float* bsu      = (const float*)d_in[18];
    const float* wnt      = (const float*)d_in[19];
    const float* bnt      = (const float*)d_in[20];
    const float* wtg      = (const float*)d_in[21];
    const float* btg      = (const float*)d_in[22];
    const float* wpr      = (const float*)d_in[23];
    const float* bpr      = (const float*)d_in[24];
    float* out = (float*)d_out;

    const int smem_gemm  = (8192 + 4096) * 4;                              // 49152 B
    const int smem_final = (4096 + 64 + 64 * 240 + 240 + 8 * 128) * 4;     // 83136 B
    cudaFuncSetAttribute(k_gemm,  cudaFuncAttributeMaxDynamicSharedMemorySize, smem_gemm);
    cudaFuncSetAttribute(k_final, cudaFuncAttributeMaxDynamicSharedMemorySize, smem_final);

    k_prepA<<<NB_M + NB_NODE + NB_HIST, 256>>>(x, input_np, output_np,     // idx 0
            in_emb, out_emb, edge_idx, w2, b2);
    k_prepB<<<(NE + 31) / 32, 256>>>(edge_nt, edge_np, edge_sc,            // idx 1
            ent_emb, enp_emb, w1, b1);
    k_scanscatter<<<1, 1024>>>(edge_idx);                                  // idx 2
    dim3 ggrid(CT / 64, (NN + 127) / 128);
    k_gemm<<<ggrid, 256, smem_gemm>>>();                                   // idx 3 (profiled)
    k_edge_apply<<<NN, 128>>>(edge_idx);                                   // idx 4
    k_final<<<(NN + 63) / 64, 256, smem_final>>>(root_w, conv_b,           // idx 5
            wsu, bsu, wnt, bnt, wtg, btg, wpr, bpr, out);
}

// round 10
// speedup vs baseline: 4.3290x; 1.3504x over previous
#include <cuda_runtime.h>
#include <cstdint>

// ---------------- problem constants ----------------
#define NN 15000          // nodes
#define NE 60000          // edges
#define ND 64             // NODE_DIM
#define HD 64             // HID
#define ED 33             // EDGE_DIM
#define CT 4160           // 65*64 real columns of M / T
#define CTP 4224          // padded column stride (33 * 128)

typedef unsigned long long ull;

__device__ __forceinline__ ull ffma2(ull a, ull b, ull c) {
    ull d;
    asm("fma.rn.f32x2 %0, %1, %2, %3;" : "=l"(d) : "l"(a), "l"(b), "l"(c));
    return d;
}
__device__ __forceinline__ ull dup2(float x) {
    ull d;
    asm("mov.b64 %0, {%1, %1};" : "=l"(d) : "f"(x));
    return d;
}
__device__ __forceinline__ float to_tf32(float x) {
    uint32_t r;
    asm("cvt.rna.tf32.f32 %0, %1;" : "=r"(r) : "f"(x));
    return __uint_as_float(r);
}
__device__ __forceinline__ void mma_tf32(float* d, const float2 aLo, const float2 aHi,
                                         const float2 b) {
    asm("mma.sync.aligned.m16n8k8.row.col.f32.tf32.tf32.f32 "
        "{%0,%1,%2,%3}, {%4,%5,%6,%7}, {%8,%9}, {%0,%1,%2,%3};"
        : "+f"(d[0]), "+f"(d[1]), "+f"(d[2]), "+f"(d[3])
        : "r"(__float_as_uint(aLo.x)), "r"(__float_as_uint(aHi.x)),
          "r"(__float_as_uint(aLo.y)), "r"(__float_as_uint(aHi.y)),
          "r"(__float_as_uint(b.x)),  "r"(__float_as_uint(b.y)));
}

// ---------------- device scratch (zero-init; consumers restore zeros) ----------------
__device__ float g_xf[NN * ND];
__device__ float g_h[NE * HD];
__device__ float g_M[ND * CTP];           // padded; cols >= CT stay 0 (never written)
__device__ float g_T[(size_t)NN * CTP];   // padded per-node tensor (253 MB)
__device__ float g_sums[NN * HD];
__device__ int   g_dcnt[NN];
__device__ int   g_hist[NN];
__device__ int   g_off[NN + 1];
__device__ int   g_cursor[NN];
__device__ int   g_sorted[NE];

// ---------------- L0: M build + node features + degree hists ----------------
#define NB_M    1040     // ceil(ND*CT/256)
#define NB_NODE 1875
#define NB_HIST 235
__global__ void k_prepA(const float* __restrict__ x,
                        const int* __restrict__ inp, const int* __restrict__ outp,
                        const float* __restrict__ in_emb, const float* __restrict__ out_emb,
                        const int* __restrict__ eidx,
                        const float* __restrict__ w2, const float* __restrict__ b2) {
    int b = blockIdx.x;
    int tid = threadIdx.x;
    if (b < NB_M) {                          // build M (padded stride)
        int idx = b * 256 + tid;
        if (idx >= ND * CT) return;
        int i = idx / CT;
        int col = idx - i * CT;
        int j = col >> 6;
        int o = col & 63;
        g_M[i * CTP + col] = (j < 64) ? w2[j * 4096 + i * 64 + o] : b2[i * 64 + o];
        return;
    }
    if (b < NB_M + NB_NODE) {                // node features
        int w = tid >> 5, l = tid & 31;
        int n = (b - NB_M) * 8 + w;
        if (n >= NN) return;
        float v0 = x[n * 32 + l];
        float v1 = (l < 16) ? in_emb[inp[n] * 16 + l]
                            : out_emb[outp[n] * 16 + (l - 16)];
        g_xf[n * 64 + l] = v0;
        g_xf[n * 64 + 32 + l] = v1;
        return;
    }
    int e = (b - NB_M - NB_NODE) * 256 + tid;
    if (e >= NE) return;
    atomicAdd(&g_hist[eidx[e]], 1);
    atomicAdd(&g_dcnt[eidx[NE + e]], 1);
}

// ---------------- L1: edge MLP h = relu(ea @ w1 + b1), 32 edges / block ----------------
__global__ void k_prepB(const int* __restrict__ e_nt, const int* __restrict__ e_np,
                        const float* __restrict__ e_sc,
                        const float* __restrict__ nt_emb, const float* __restrict__ np_emb,
                        const float* __restrict__ w1, const float* __restrict__ b1) {
    __shared__ float w1s[ED * 64];
    __shared__ float b1s[64];
    __shared__ float eas[8][34];
    int tid = threadIdx.x;
    for (int i = tid; i < ED * 64; i += 256) w1s[i] = w1[i];
    if (tid < 64) b1s[tid] = b1[tid];
    __syncthreads();
    int w = tid >> 5, l = tid & 31;
#pragma unroll
    for (int pass = 0; pass < 4; pass++) {
        int e = (blockIdx.x * 4 + pass) * 8 + w;
        if (e >= NE) break;
        if (l < 16) eas[w][l] = nt_emb[e_nt[e] * 16 + l];
        else        eas[w][l] = np_emb[e_np[e] * 16 + (l - 16)];
        if (l == 0) eas[w][32] = e_sc[e];
        __syncwarp();
        int o0 = l, o1 = l + 32;
        float a0 = b1s[o0], a1 = b1s[o1];
#pragma unroll
        for (int k = 0; k < ED; k++) {
            float v = eas[w][k];
            a0 = fmaf(v, w1s[k * 64 + o0], a0);
            a1 = fmaf(v, w1s[k * 64 + o1], a1);
        }
        g_h[e * 64 + o0] = fmaxf(a0, 0.f);
        g_h[e * 64 + o1] = fmaxf(a1, 0.f);
        __syncwarp();
    }
}

// ---------------- L2: CSR scan (single block); zeroes g_hist ----------------
__global__ void k_scan() {
    __shared__ int warp_sums[32];
    __shared__ int s_carry;
    int tid = threadIdx.x;
    int lane = tid & 31, wid = tid >> 5;
    if (tid == 0) { s_carry = 0; g_off[0] = 0; }
    __syncthreads();
    for (int base = 0; base < NN; base += 1024) {
        int i = base + tid;
        int v = (i < NN) ? g_hist[i] : 0;
        if (i < NN) g_hist[i] = 0;          // restore zero for next replay
        int xv = v;
#pragma unroll
        for (int d = 1; d < 32; d <<= 1) {
            int y = __shfl_up_sync(0xffffffffu, xv, d);
            if (lane >= d) xv += y;
        }
        if (lane == 31) warp_sums[wid] = xv;
        __syncthreads();
        if (tid < 32) {
            int w = warp_sums[tid];
#pragma unroll
            for (int d = 1; d < 32; d <<= 1) {
                int y = __shfl_up_sync(0xffffffffu, w, d);
                if (tid >= d) w += y;
            }
            warp_sums[tid] = w;
        }
        __syncthreads();
        int incl = xv + ((wid > 0) ? warp_sums[wid - 1] : 0) + s_carry;
        if (i < NN) { g_off[i + 1] = incl; g_cursor[i] = incl - v; }
        __syncthreads();
        if (tid == 0) s_carry += warp_sums[31];
        __syncthreads();
    }
}

// ---------------- L4: parallel scatter of edge ids ----------------
__global__ void k_scatter(const int* __restrict__ eidx) {
    int e = blockIdx.x * blockDim.x + threadIdx.x;
    if (e >= NE) return;
    int pos = atomicAdd(&g_cursor[eidx[e]], 1);
    g_sorted[pos] = e;
}

// ---------------- L3 (PROFILED): tf32 tensor-core GEMM  T = g_xf @ g_M ----------------
// Block tile 128m x 128n, K=64. 256 threads = 8 warps (4m x 2n); warp tile 32m x 64n.
// As[kk][mt(8)][r(16)][p(8)], kk-stride 1036 (bank-skew); p = (kc&3)*2 + (kc>>2).
// Bs[kk][nt(16)][nn(8)][p(8)], kk-stride 1024.
#define AS_KK 1036
#define AS_SIZE (7 * AS_KK + 1024)      // 8276
#define SM_GEMM_FLOATS (AS_SIZE + 8192) // 16468
__global__ __launch_bounds__(256) void k_gemm() {
    extern __shared__ float sm[];
    float* As = sm;
    float* Bs = sm + AS_SIZE;
    int tid = threadIdx.x;
    int c0 = blockIdx.x * 128;
    int r0 = blockIdx.y * 128;

    // stage A: thread handles 4 (m, kk) units; 2x LDG.128 + permuted 2x STS.128
#pragma unroll
    for (int t = 0; t < 4; t++) {
        int idx = t * 256 + tid;
        int m = idx >> 3, kk = idx & 7;
        int row = r0 + m;
        float4 lo = make_float4(0.f, 0.f, 0.f, 0.f), hi = lo;
        if (row < NN) {
            lo = *(const float4*)&g_xf[row * 64 + kk * 8];
            hi = *(const float4*)&g_xf[row * 64 + kk * 8 + 4];
        }
        float* dst = As + kk * AS_KK + ((m >> 4) * 16 + (m & 15)) * 8;
        dst[0] = to_tf32(lo.x); dst[1] = to_tf32(hi.x);
        dst[2] = to_tf32(lo.y); dst[3] = to_tf32(hi.y);
        dst[4] = to_tf32(lo.z); dst[5] = to_tf32(hi.z);
        dst[6] = to_tf32(lo.w); dst[7] = to_tf32(hi.w);
    }
    // stage B: thread handles 4 (n, kk) units; 8 coalesced LDG + 2x STS.128
#pragma unroll
    for (int t = 0; t < 4; t++) {
        int idx = t * 256 + tid;
        int n = idx & 127, kk = idx >> 7;
        const float* src = g_M + (size_t)(kk * 8) * CTP + c0 + n;
        float v[8];
#pragma unroll
        for (int kc = 0; kc < 8; kc++) v[kc] = src[(size_t)kc * CTP];
        float* dst = Bs + ((kk * 16 + (n >> 3)) * 8 + (n & 7)) * 8;
        dst[0] = to_tf32(v[0]); dst[1] = to_tf32(v[4]);
        dst[2] = to_tf32(v[1]); dst[3] = to_tf32(v[5]);
        dst[4] = to_tf32(v[2]); dst[5] = to_tf32(v[6]);
        dst[6] = to_tf32(v[3]); dst[7] = to_tf32(v[7]);
    }
    __syncthreads();

    int warp = tid >> 5, lane = tid & 31;
    int wm = warp & 3;              // 4 m-groups of 32 rows
    int wn = warp >> 2;             // 2 n-groups of 64 cols
    int r = lane >> 2, c = lane & 3;

    float acc[2][8][4];
#pragma unroll
    for (int i = 0; i < 2; i++)
#pragma unroll
        for (int j = 0; j < 8; j++)
#pragma unroll
            for (int q = 0; q < 4; q++) acc[i][j][q] = 0.f;

#pragma unroll
    for (int kk = 0; kk < 8; kk++) {
        float2 aLo[2], aHi[2], bv[8];
#pragma unroll
        for (int i = 0; i < 2; i++) {
            const float* ab = As + kk * AS_KK + ((wm * 2 + i) * 16) * 8;
            aLo[i] = *(const float2*)&ab[r * 8 + c * 2];
            aHi[i] = *(const float2*)&ab[(r + 8) * 8 + c * 2];
        }
#pragma unroll
        for (int j = 0; j < 8; j++) {
            int nt = wn * 8 + j;
            bv[j] = *(const float2*)&Bs[((kk * 16 + nt) * 8 + r) * 8 + c * 2];
        }
#pragma unroll
        for (int i = 0; i < 2; i++)
#pragma unroll
            for (int j = 0; j < 8; j++)
                mma_tf32(acc[i][j], aLo[i], aHi[i], bv[j]);
    }

#pragma unroll
    for (int i = 0; i < 2; i++) {
        int rb = r0 + wm * 32 + i * 16 + r;
#pragma unroll
        for (int j = 0; j < 8; j++) {
            int col = c0 + wn * 64 + j * 8 + c * 2;
            if (rb < NN)
                *(float2*)&g_T[(size_t)rb * CTP + col] = make_float2(acc[i][j][0], acc[i][j][1]);
            if (rb + 8 < NN)
                *(float2*)&g_T[(size_t)(rb + 8) * CTP + col] = make_float2(acc[i][j][2], acc[i][j][3]);
        }
    }
}

// ---------------- L5: per-src-node edge apply (1 block / node, T row in smem) ----------------
__global__ void k_edge_apply(const int* __restrict__ eidx) {
    __shared__ __align__(16) float ts[CT];     // 16640 B (T row for this src)
    __shared__ ull hd[8][64];                  // 4096 B (packed dup h per edge)
    __shared__ int dsts[8];
    int n = blockIdx.x;
    int beg = g_off[n], end = g_off[n + 1];
    if (beg == end) return;
    int tid = threadIdx.x;                     // 128 threads
    const float4* Tp = (const float4*)(g_T + (size_t)n * CTP);
    float4* tsp = (float4*)ts;
    for (int i = tid; i < CT / 4; i += 128) tsp[i] = Tp[i];
    __syncthreads();

    int q = tid >> 4;          // edge slot 0..7
    int l16 = tid & 15;
    int o = l16 * 4;           // 4 outputs o..o+3
    const ulonglong2* ts2 = (const ulonglong2*)ts;

    for (int p = beg; p < end; p += 8) {
        int idx = p + q;
        int e = -1;
        if (idx < end) {
            e = g_sorted[idx];
            const float* hp = g_h + e * 64;
#pragma unroll
            for (int t = 0; t < 4; t++) hd[q][o + t] = dup2(hp[o + t]);
            if (l16 == 0) dsts[q] = eidx[NE + e];
        }
        __syncthreads();
        if (e >= 0) {
            ull acc0 = *(const ull*)&ts[4096 + o];      // b2 row (h'[64]=1)
            ull acc1 = *(const ull*)&ts[4096 + o + 2];
#pragma unroll 16
            for (int j = 0; j < 64; j++) {
                ull h2 = hd[q][j];
                ulonglong2 t4 = ts2[j * 16 + l16];
                acc0 = ffma2(h2, t4.x, acc0);
                acc1 = ffma2(h2, t4.y, acc1);
            }
            int dst = dsts[q];
            float* sp = g_sums + dst * 64 + o;
            atomicAdd(sp + 0, __uint_as_float((unsigned)acc0));
            atomicAdd(sp + 1, __uint_as_float((unsigned)(acc0 >> 32)));
            atomicAdd(sp + 2, __uint_as_float((unsigned)acc1));
            atomicAdd(sp + 3, __uint_as_float((unsigned)(acc1 >> 32)));
        }
        __syncthreads();
    }
}

// ---------------- L6: scatter-mean + root + ReLU + 4 heads; 64 nodes/block ----------------
__global__ void k_final(const float* __restrict__ root_w, const float* __restrict__ conv_b,
                        const float* __restrict__ wsu, const float* __restrict__ bsu,
                        const float* __restrict__ wnt, const float* __restrict__ bnt,
                        const float* __restrict__ wtg, const float* __restrict__ btg,
                        const float* __restrict__ wpr, const float* __restrict__ bpr,
                        float* __restrict__ out) {
    extern __shared__ float sm[];
    float* rw = sm;                  // 4096
    float* cb = rw + 4096;           // 64
    float* Wc = cb + 64;             // 64*240
    float* bc = Wc + 64 * 240;       // 240
    float* stage = bc + 240;         // 8 * 128
    int tid = threadIdx.x;
    for (int i = tid; i < 4096; i += 256) rw[i] = root_w[i];
    if (tid < 64) cb[tid] = conv_b[tid];
    for (int i = tid; i < 64 * 16; i += 256)  { int r = i >> 4, c = i & 15;  Wc[r * 240 + c]       = wsu[i]; }
    for (int i = tid; i < 64 * 32; i += 256)  { int r = i >> 5, c = i & 31;  Wc[r * 240 + 16 + c]  = wnt[i]; }
    for (int i = tid; i < 64 * 64; i += 256)  { int r = i >> 6, c = i & 63;  Wc[r * 240 + 48 + c]  = wtg[i]; }
    for (int i = tid; i < 64 * 128; i += 256) { int r = i >> 7, c = i & 127; Wc[r * 240 + 112 + c] = wpr[i]; }
    if (tid < 16)       bc[tid] = bsu[tid];
    else if (tid < 48)  bc[tid] = bnt[tid - 16];
    else if (tid < 112) bc[tid] = btg[tid - 48];
    else if (tid < 240) bc[tid] = bpr[tid - 112];
    __syncthreads();

    int w = tid >> 5, l = tid & 31;
    float* xs = stage + w * 128;
    float* os = xs + 64;

#pragma unroll
    for (int pass = 0; pass < 8; pass++) {
        int n = blockIdx.x * 64 + pass * 8 + w;
        if (n >= NN) break;
        xs[l] = g_xf[n * 64 + l];
        xs[l + 32] = g_xf[n * 64 + 32 + l];
        __syncwarp();

        float inv = 1.f / fmaxf((float)g_dcnt[n], 1.f);
        if (l == 0) g_dcnt[n] = 0;                          // restore zero
#pragma unroll
        for (int half = 0; half < 2; half++) {
            int o = l + 32 * half;
            float sv = g_sums[n * 64 + o];
            g_sums[n * 64 + o] = 0.f;                       // restore zero
            float acc = cb[o] + sv * inv;
#pragma unroll 8
            for (int i = 0; i < 64; i++) acc = fmaf(xs[i], rw[i * 64 + o], acc);
            os[o] = fmaxf(acc, 0.f);
        }
        __syncwarp();

#pragma unroll
        for (int q = 0; q < 8; q++) {
            int t = l + 32 * q;
            if (t < 240) {
                float acc = bc[t];
#pragma unroll 8
                for (int i = 0; i < 64; i++) acc = fmaf(os[i], Wc[i * 240 + t], acc);
                if (t < 16)       out[n * 16 + t] = acc;
                else if (t < 48)  out[240000  + n * 32  + (t - 16)]  = acc;
                else if (t < 112) out[720000  + n * 64  + (t - 48)]  = acc;
                else              out[1680000 + n * 128 + (t - 112)] = acc;
            }
        }
        __syncwarp();
    }
}

// ---------------- launch ----------------
extern "C" void kernel_launch(void* const* d_in, const int* in_sizes, int n_in,
                              void* d_out, int out_size) {
    const float* x        = (const float*)d_in[0];
    const int*   input_np = (const int*)  d_in[1];
    const int*   output_np= (const int*)  d_in[2];
    const int*   edge_idx = (const int*)  d_in[3];
    const int*   edge_nt  = (const int*)  d_in[4];
    const int*   edge_np  = (const int*)  d_in[5];
    const float* edge_sc  = (const float*)d_in[6];
    const float* in_emb   = (const float*)d_in[7];
    const float* out_emb  = (const float*)d_in[8];
    const float* enp_emb  = (const float*)d_in[9];
    const float* ent_emb  = (const float*)d_in[10];
    const float* w1       = (const float*)d_in[11];
    const float* b1       = (const float*)d_in[12];
    const float* w2       = (const float*)d_in[13];
    const float* b2       = (const float*)d_in[14];
    const float* root_w   = (const float*)d_in[15];
    const float* conv_b   = (const float*)d_in[16];
    const float* wsu      = (const float*)d_in[17];
    const float* bsu      = (const float*)d_in[18];
    const float* wnt      = (const float*)d_in[19];
    const float* bnt      = (const float*)d_in[20];
    const float* wtg      = (const float*)d_in[21];
    const float* btg      = (const float*)d_in[22];
    const float* wpr      = (const float*)d_in[23];
    const float* bpr      = (const float*)d_in[24];
    float* out = (float*)d_out;

    const int smem_gemm  = SM_GEMM_FLOATS * 4;                             // 65872 B
    const int smem_final = (4096 + 64 + 64 * 240 + 240 + 8 * 128) * 4;     // 83136 B
    cudaFuncSetAttribute(k_gemm,  cudaFuncAttributeMaxDynamicSharedMemorySize, smem_gemm);
    cudaFuncSetAttribute(k_final, cudaFuncAttributeMaxDynamicSharedMemorySize, smem_final);

    k_prepA<<<NB_M + NB_NODE + NB_HIST, 256>>>(x, input_np, output_np,     // idx 0
            in_emb, out_emb, edge_idx, w2, b2);
    k_prepB<<<(NE + 31) / 32, 256>>>(edge_nt, edge_np, edge_sc,            // idx 1
            ent_emb, enp_emb, w1, b1);
    k_scan<<<1, 1024>>>();                                                 // idx 2
    dim3 ggrid(33, (NN + 127) / 128);
    k_gemm<<<ggrid, 256, smem_gemm>>>();                                   // idx 3 (profiled)
    k_scatter<<<(NE + 255) / 256, 256>>>(edge_idx);                        // idx 4
    k_edge_apply<<<NN, 128>>>(edge_idx);                                   // idx 5
    k_final<<<(NN + 63) / 64, 256, smem_final>>>(root_w, conv_b,           // idx 6
            wsu, bsu, wnt, bnt, wtg, btg, wpr, bpr, out);
}